// round 1
// baseline (speedup 1.0000x reference)
#include <cuda_runtime.h>
#include <cuda_bf16.h>
#include <cstddef>

#define Bsz 32
#define Ssz 128
#define Tsz 64
#define T1  63
#define Ed  256
#define Hd  512
#define Vsz 32000
#define FH  2048   // 4*H

// ---------------- scratch (device globals; no allocation allowed) ----------------
__device__ __align__(16) float g_src_emb[(size_t)Ssz * Bsz * Ed];    // rows (s,b)
__device__ __align__(16) float g_dec_in [(size_t)T1  * Bsz * Ed];    // rows (t,b)
__device__ __align__(16) float g_enc_xg [(size_t)Ssz * Bsz * FH];    // rows (s,b)
__device__ __align__(16) float g_dec_xg [(size_t)T1  * Bsz * FH];    // rows (t,b)
__device__ __align__(16) float g_enc_out[(size_t)Bsz * Ssz * Hd];    // rows (b,s)
__device__ __align__(16) float g_enc_proj[(size_t)Bsz * Ssz * Hd];   // rows (b,s)
__device__ __align__(16) float g_hs     [(size_t)Bsz * T1  * Hd];    // rows (b,t)
__device__ __align__(16) float g_hA[Bsz * Hd];
__device__ __align__(16) float g_hB[Bsz * Hd];
__device__ __align__(16) float g_c [Bsz * Hd];
__device__ __align__(16) float g_ctx[Bsz * Hd];

__device__ __forceinline__ float sigf(float x) { return 1.0f / (1.0f + expf(-x)); }

// ---------------- init: zero h, c ----------------
__global__ void init_state_kernel() {
    int i = blockIdx.x * blockDim.x + threadIdx.x;
    if (i < Bsz * Hd) { g_hA[i] = 0.f; g_c[i] = 0.f; }
}

// ---------------- embedding gathers ----------------
__global__ void gather_src_kernel(const int* __restrict__ src, const float* __restrict__ embed) {
    int row = blockIdx.x;              // row = s*B + b
    int s = row >> 5, b = row & 31;
    int idx = src[b * Ssz + s];
    g_src_emb[(size_t)row * Ed + threadIdx.x] = embed[(size_t)idx * Ed + threadIdx.x];
}
__global__ void gather_dec_kernel(const int* __restrict__ tgt, const float* __restrict__ embed) {
    int row = blockIdx.x;              // row = t*B + b
    int t = row >> 5, b = row & 31;
    int idx = tgt[b * Tsz + t];        // tgt[:, :-1]
    g_dec_in[(size_t)row * Ed + threadIdx.x] = embed[(size_t)idx * Ed + threadIdx.x];
}

// ---------------- generic SGEMM: C[m,n] = bias1[n](+bias2[n]) + sum_k A[m,k]*W[n, woff+k] ----------------
// A: M x K row-major (lda=K). W rows: ldw stride, column offset woff. 128x128 blocktile, 8x8/thread.
__global__ void __launch_bounds__(256) sgemm_bias_kernel(
    const float* __restrict__ A, int K,
    const float* __restrict__ W, int ldw, int woff,
    const float* __restrict__ b1, const float* __restrict__ b2,
    float* __restrict__ C, int M, int N)
{
    __shared__ float As[8][128];
    __shared__ float Bs[8][128];
    const int bm = blockIdx.y * 128;
    const int bn = blockIdx.x * 128;
    const int t  = threadIdx.x;
    const int tr = (t >> 4) * 8;      // 0..120, m-offset within tile
    const int tc = (t & 15) * 8;      // 0..120, n-offset within tile
    const int lr = t >> 1;            // 0..127
    const int lc = (t & 1) * 4;       // 0 or 4

    float acc[8][8];
    #pragma unroll
    for (int i = 0; i < 8; i++)
        #pragma unroll
        for (int j = 0; j < 8; j++) acc[i][j] = 0.f;

    const bool aValid = (bm + lr) < M;     // N is always a multiple of 128 here
    const float* aRow = A + (size_t)(bm + lr) * K + lc;
    const float* wRow = W + (size_t)(bn + lr) * ldw + woff + lc;

    for (int k0 = 0; k0 < K; k0 += 8) {
        float4 av = aValid ? *(const float4*)(aRow + k0) : make_float4(0.f, 0.f, 0.f, 0.f);
        float4 wv = *(const float4*)(wRow + k0);
        As[lc + 0][lr] = av.x; As[lc + 1][lr] = av.y; As[lc + 2][lr] = av.z; As[lc + 3][lr] = av.w;
        Bs[lc + 0][lr] = wv.x; Bs[lc + 1][lr] = wv.y; Bs[lc + 2][lr] = wv.z; Bs[lc + 3][lr] = wv.w;
        __syncthreads();
        #pragma unroll
        for (int kk = 0; kk < 8; kk++) {
            float a[8], bb[8];
            *(float4*)(a)      = *(const float4*)&As[kk][tr];
            *(float4*)(a + 4)  = *(const float4*)&As[kk][tr + 4];
            *(float4*)(bb)     = *(const float4*)&Bs[kk][tc];
            *(float4*)(bb + 4) = *(const float4*)&Bs[kk][tc + 4];
            #pragma unroll
            for (int i = 0; i < 8; i++)
                #pragma unroll
                for (int j = 0; j < 8; j++) acc[i][j] += a[i] * bb[j];
        }
        __syncthreads();
    }

    float bias[8];
    #pragma unroll
    for (int j = 0; j < 8; j++) {
        int n = bn + tc + j;
        bias[j] = b1[n] + (b2 ? b2[n] : 0.f);
    }
    #pragma unroll
    for (int i = 0; i < 8; i++) {
        int m = bm + tr + i;
        if (m >= M) break;
        float* cp = C + (size_t)m * N + bn + tc;
        #pragma unroll
        for (int j = 0; j < 8; j++) cp[j] = acc[i][j] + bias[j];
    }
}

// ---------------- encoder recurrent step ----------------
// grid (32 hGroups of 16, 4 bGroups of 8), 256 threads
__global__ void __launch_bounds__(256) enc_step_kernel(
    const float* __restrict__ Whh,
    const float* __restrict__ h_in, float* __restrict__ h_out, int s)
{
    __shared__ float h_s[8][Hd];
    __shared__ float gates_s[512];
    const int hG = blockIdx.x, bG = blockIdx.y;
    const int t = threadIdx.x;

    for (int i = t; i < 8 * Hd; i += 256) {
        int bl = i >> 9, k = i & (Hd - 1);
        h_s[bl][k] = h_in[(bG * 8 + bl) * Hd + k];
    }
    __syncthreads();

    const int jl = t & 63;             // gate*16 + hoff
    const int bl0 = t >> 6;            // 0..3
    const int gate = jl >> 4, hoff = jl & 15;
    const int j = gate * Hd + hG * 16 + hoff;
    const int b0 = bG * 8 + bl0, b1i = b0 + 4;
    const float4* wv = (const float4*)(Whh + (size_t)j * Hd);

    float acc0 = g_enc_xg[((size_t)s * Bsz + b0)  * FH + j];
    float acc1 = g_enc_xg[((size_t)s * Bsz + b1i) * FH + j];
    #pragma unroll 4
    for (int k4 = 0; k4 < Hd / 4; k4++) {
        float4 w = wv[k4];
        float4 h0 = *(const float4*)&h_s[bl0][k4 * 4];
        float4 h1 = *(const float4*)&h_s[bl0 + 4][k4 * 4];
        acc0 += h0.x * w.x + h0.y * w.y + h0.z * w.z + h0.w * w.w;
        acc1 += h1.x * w.x + h1.y * w.y + h1.z * w.z + h1.w * w.w;
    }
    gates_s[bl0 * 64 + jl] = acc0;
    gates_s[(bl0 + 4) * 64 + jl] = acc1;
    __syncthreads();

    if (t < 128) {
        int bl = t >> 4, ho = t & 15;
        float ig = gates_s[bl * 64 + 0  + ho];
        float fg = gates_s[bl * 64 + 16 + ho];
        float gg = gates_s[bl * 64 + 32 + ho];
        float og = gates_s[bl * 64 + 48 + ho];
        int b = bG * 8 + bl, h = hG * 16 + ho;
        float cv = sigf(fg) * g_c[b * Hd + h] + sigf(ig) * tanhf(gg);
        float hn = sigf(og) * tanhf(cv);
        g_c[b * Hd + h] = cv;
        h_out[b * Hd + h] = hn;
        g_enc_out[((size_t)b * Ssz + s) * Hd + h] = hn;
    }
}

// ---------------- attention (one block per batch element) ----------------
__global__ void __launch_bounds__(256) attn_kernel(
    const float* __restrict__ h_in,
    const float* __restrict__ attn_W,
    const float* __restrict__ attn_v)
{
    const int b = blockIdx.x;
    const int t = threadIdx.x;
    __shared__ float h_s[Hd];
    __shared__ float v_s[Hd];
    __shared__ float hp_s[Hd];
    __shared__ float w_s[Ssz];

    for (int i = t; i < Hd; i += 256) { h_s[i] = h_in[b * Hd + i]; v_s[i] = attn_v[i]; }
    __syncthreads();

    // hproj = h @ W_h.T  (W_h = attn_W[:, :H], row stride 2H)
    for (int kk = t; kk < Hd; kk += 256) {
        const float4* wr = (const float4*)(attn_W + (size_t)kk * (2 * Hd));
        float acc = 0.f;
        #pragma unroll 4
        for (int k4 = 0; k4 < Hd / 4; k4++) {
            float4 w = wr[k4];
            float4 hh = *(const float4*)&h_s[k4 * 4];
            acc += hh.x * w.x + hh.y * w.y + hh.z * w.z + hh.w * w.w;
        }
        hp_s[kk] = acc;
    }
    __syncthreads();

    // scores[s] = sum_k tanh(hproj[k] + enc_proj[b,s,k]) * v[k]
    const int warp = t >> 5, lane = t & 31;
    for (int s = warp; s < Ssz; s += 8) {
        const float* ep = g_enc_proj + ((size_t)b * Ssz + s) * Hd;
        float acc = 0.f;
        for (int k = lane; k < Hd; k += 32)
            acc += tanhf(hp_s[k] + ep[k]) * v_s[k];
        #pragma unroll
        for (int off = 16; off; off >>= 1) acc += __shfl_xor_sync(0xffffffffu, acc, off);
        if (!lane) w_s[s] = acc;
    }
    __syncthreads();

    // softmax over S=128 (warp 0)
    if (warp == 0) {
        float v0 = w_s[lane], v1 = w_s[lane + 32], v2 = w_s[lane + 64], v3 = w_s[lane + 96];
        float m = fmaxf(fmaxf(v0, v1), fmaxf(v2, v3));
        #pragma unroll
        for (int off = 16; off; off >>= 1) m = fmaxf(m, __shfl_xor_sync(0xffffffffu, m, off));
        float e0 = __expf(v0 - m), e1 = __expf(v1 - m), e2 = __expf(v2 - m), e3 = __expf(v3 - m);
        float sum = e0 + e1 + e2 + e3;
        #pragma unroll
        for (int off = 16; off; off >>= 1) sum += __shfl_xor_sync(0xffffffffu, sum, off);
        float inv = 1.f / sum;
        w_s[lane] = e0 * inv; w_s[lane + 32] = e1 * inv;
        w_s[lane + 64] = e2 * inv; w_s[lane + 96] = e3 * inv;
    }
    __syncthreads();

    // context[h] = sum_s w[s] * enc_out[b,s,h]
    for (int h = t; h < Hd; h += 256) {
        const float* eo = g_enc_out + (size_t)b * Ssz * Hd + h;
        float acc = 0.f;
        #pragma unroll 4
        for (int s = 0; s < Ssz; s++) acc += w_s[s] * eo[(size_t)s * Hd];
        g_ctx[b * Hd + h] = acc;
    }
}

// ---------------- decoder recurrent step ----------------
__global__ void __launch_bounds__(256) dec_step_kernel(
    const float* __restrict__ Wih,   // (4H, E+H)
    const float* __restrict__ Whh,   // (4H, H)
    const float* __restrict__ h_in, float* __restrict__ h_out, int tstep)
{
    __shared__ float h_s[8][Hd];
    __shared__ float ctx_s[8][Hd];
    __shared__ float gates_s[512];
    const int hG = blockIdx.x, bG = blockIdx.y;
    const int t = threadIdx.x;

    for (int i = t; i < 8 * Hd; i += 256) {
        int bl = i >> 9, k = i & (Hd - 1);
        h_s[bl][k]   = h_in[(bG * 8 + bl) * Hd + k];
        ctx_s[bl][k] = g_ctx[(bG * 8 + bl) * Hd + k];
    }
    __syncthreads();

    const int jl = t & 63;
    const int bl0 = t >> 6;
    const int gate = jl >> 4, hoff = jl & 15;
    const int j = gate * Hd + hG * 16 + hoff;
    const int b0 = bG * 8 + bl0, b1i = b0 + 4;
    const float4* w1v = (const float4*)(Whh + (size_t)j * Hd);
    const float4* w2v = (const float4*)(Wih + (size_t)j * (Ed + Hd) + Ed);

    float acc0 = g_dec_xg[((size_t)tstep * Bsz + b0)  * FH + j];
    float acc1 = g_dec_xg[((size_t)tstep * Bsz + b1i) * FH + j];
    #pragma unroll 4
    for (int k4 = 0; k4 < Hd / 4; k4++) {
        float4 wa = w1v[k4];
        float4 wb = w2v[k4];
        float4 h0 = *(const float4*)&h_s[bl0][k4 * 4];
        float4 h1 = *(const float4*)&h_s[bl0 + 4][k4 * 4];
        float4 c0 = *(const float4*)&ctx_s[bl0][k4 * 4];
        float4 c1 = *(const float4*)&ctx_s[bl0 + 4][k4 * 4];
        acc0 += h0.x * wa.x + h0.y * wa.y + h0.z * wa.z + h0.w * wa.w;
        acc0 += c0.x * wb.x + c0.y * wb.y + c0.z * wb.z + c0.w * wb.w;
        acc1 += h1.x * wa.x + h1.y * wa.y + h1.z * wa.z + h1.w * wa.w;
        acc1 += c1.x * wb.x + c1.y * wb.y + c1.z * wb.z + c1.w * wb.w;
    }
    gates_s[bl0 * 64 + jl] = acc0;
    gates_s[(bl0 + 4) * 64 + jl] = acc1;
    __syncthreads();

    if (t < 128) {
        int bl = t >> 4, ho = t & 15;
        float ig = gates_s[bl * 64 + 0  + ho];
        float fg = gates_s[bl * 64 + 16 + ho];
        float gg = gates_s[bl * 64 + 32 + ho];
        float og = gates_s[bl * 64 + 48 + ho];
        int b = bG * 8 + bl, h = hG * 16 + ho;
        float cv = sigf(fg) * g_c[b * Hd + h] + sigf(ig) * tanhf(gg);
        float hn = sigf(og) * tanhf(cv);
        g_c[b * Hd + h] = cv;
        h_out[b * Hd + h] = hn;
        g_hs[((size_t)b * T1 + tstep) * Hd + h] = hn;
    }
}

// ---------------- launch ----------------
extern "C" void kernel_launch(void* const* d_in, const int* in_sizes, int n_in,
                              void* d_out, int out_size)
{
    const int*   src     = (const int*)d_in[0];
    const int*   tgt     = (const int*)d_in[1];
    const float* embed   = (const float*)d_in[2];
    const float* enc_Wih = (const float*)d_in[3];
    const float* enc_Whh = (const float*)d_in[4];
    const float* enc_bih = (const float*)d_in[5];
    const float* enc_bhh = (const float*)d_in[6];
    const float* dec_Wih = (const float*)d_in[7];
    const float* dec_Whh = (const float*)d_in[8];
    const float* dec_bih = (const float*)d_in[9];
    const float* dec_bhh = (const float*)d_in[10];
    const float* attn_W  = (const float*)d_in[11];
    const float* attn_b  = (const float*)d_in[12];
    const float* attn_v  = (const float*)d_in[13];
    const float* fc_W    = (const float*)d_in[14];
    const float* fc_b    = (const float*)d_in[15];
    float* out = (float*)d_out;

    float *p_src_emb, *p_dec_in, *p_enc_xg, *p_dec_xg, *p_enc_out, *p_enc_proj, *p_hs, *p_hA, *p_hB;
    cudaGetSymbolAddress((void**)&p_src_emb,  g_src_emb);
    cudaGetSymbolAddress((void**)&p_dec_in,   g_dec_in);
    cudaGetSymbolAddress((void**)&p_enc_xg,   g_enc_xg);
    cudaGetSymbolAddress((void**)&p_dec_xg,   g_dec_xg);
    cudaGetSymbolAddress((void**)&p_enc_out,  g_enc_out);
    cudaGetSymbolAddress((void**)&p_enc_proj, g_enc_proj);
    cudaGetSymbolAddress((void**)&p_hs,       g_hs);
    cudaGetSymbolAddress((void**)&p_hA,       g_hA);
    cudaGetSymbolAddress((void**)&p_hB,       g_hB);

    // init h, c = 0
    init_state_kernel<<<(Bsz * Hd + 255) / 256, 256>>>();

    // embedding gathers
    gather_src_kernel<<<Ssz * Bsz, Ed>>>(src, embed);
    gather_dec_kernel<<<T1 * Bsz, Ed>>>(tgt, embed);

    // input-side gate GEMMs (hoisted out of the scans)
    {
        dim3 grid(FH / 128, (Ssz * Bsz + 127) / 128);
        sgemm_bias_kernel<<<grid, 256>>>(p_src_emb, Ed, enc_Wih, Ed, 0,
                                         enc_bih, enc_bhh, p_enc_xg, Ssz * Bsz, FH);
    }
    {
        dim3 grid(FH / 128, (T1 * Bsz + 127) / 128);
        sgemm_bias_kernel<<<grid, 256>>>(p_dec_in, Ed, dec_Wih, Ed + Hd, 0,
                                         dec_bih, dec_bhh, p_dec_xg, T1 * Bsz, FH);
    }

    // encoder scan
    float* hin = p_hA;
    float* hout = p_hB;
    for (int s = 0; s < Ssz; s++) {
        enc_step_kernel<<<dim3(Hd / 16, Bsz / 8), 256>>>(enc_Whh, hin, hout, s);
        float* tmp = hin; hin = hout; hout = tmp;
    }

    // enc_proj = enc_out @ W_e.T + attn_b   (W_e = attn_W[:, H:])
    {
        dim3 grid(Hd / 128, (Bsz * Ssz + 127) / 128);
        sgemm_bias_kernel<<<grid, 256>>>(p_enc_out, Hd, attn_W, 2 * Hd, Hd,
                                         attn_b, nullptr, p_enc_proj, Bsz * Ssz, Hd);
    }

    // decoder scan
    for (int t = 0; t < T1; t++) {
        attn_kernel<<<Bsz, 256>>>(hin, attn_W, attn_v);
        dec_step_kernel<<<dim3(Hd / 16, Bsz / 8), 256>>>(dec_Wih, dec_Whh, hin, hout, t);
        float* tmp = hin; hin = hout; hout = tmp;
    }

    // final FC: out[b,t,v] = hs[b,t,:] @ fc_W[v,:] + fc_b[v]
    {
        dim3 grid(Vsz / 128, (Bsz * T1 + 127) / 128);
        sgemm_bias_kernel<<<grid, 256>>>(p_hs, Hd, fc_W, Hd, 0,
                                         fc_b, nullptr, out, Bsz * T1, Vsz);
    }
}

// round 2
// speedup vs baseline: 1.0026x; 1.0026x over previous
#include <cuda_runtime.h>
#include <cuda_bf16.h>
#include <cstddef>

#define Bsz 32
#define Ssz 128
#define Tsz 64
#define T1  63
#define Ed  256
#define Hd  512
#define Vsz 32000
#define FH  2048   // 4*H

// ---------------- scratch (device globals; no allocation allowed) ----------------
__device__ __align__(16) float g_src_emb[(size_t)Ssz * Bsz * Ed];    // rows (s,b)
__device__ __align__(16) float g_dec_in [(size_t)T1  * Bsz * Ed];    // rows (t,b)
__device__ __align__(16) float g_enc_xg [(size_t)Ssz * Bsz * FH];    // rows (s,b)
__device__ __align__(16) float g_dec_xg [(size_t)T1  * Bsz * FH];    // rows (t,b)
__device__ __align__(16) float g_enc_out[(size_t)Bsz * Ssz * Hd];    // rows (b,s)
__device__ __align__(16) float g_enc_proj[(size_t)Bsz * Ssz * Hd];   // rows (b,s)
__device__ __align__(16) float g_hs     [(size_t)Bsz * T1  * Hd];    // rows (b,t)
__device__ __align__(16) float g_hA[Bsz * Hd];
__device__ __align__(16) float g_hB[Bsz * Hd];
__device__ __align__(16) float g_c [Bsz * Hd];
__device__ __align__(16) float g_ctx[Bsz * Hd];

__device__ __forceinline__ float sigf(float x) { return 1.0f / (1.0f + expf(-x)); }

// ---------------- init: zero h, c ----------------
__global__ void init_state_kernel() {
    int i = blockIdx.x * blockDim.x + threadIdx.x;
    if (i < Bsz * Hd) { g_hA[i] = 0.f; g_c[i] = 0.f; }
}

// ---------------- embedding gathers ----------------
__global__ void gather_src_kernel(const int* __restrict__ src, const float* __restrict__ embed) {
    int row = blockIdx.x;              // row = s*B + b
    int s = row >> 5, b = row & 31;
    int idx = src[b * Ssz + s];
    g_src_emb[(size_t)row * Ed + threadIdx.x] = embed[(size_t)idx * Ed + threadIdx.x];
}
__global__ void gather_dec_kernel(const int* __restrict__ tgt, const float* __restrict__ embed) {
    int row = blockIdx.x;              // row = t*B + b
    int t = row >> 5, b = row & 31;
    int idx = tgt[b * Tsz + t];        // tgt[:, :-1]
    g_dec_in[(size_t)row * Ed + threadIdx.x] = embed[(size_t)idx * Ed + threadIdx.x];
}

// ---------------- generic SGEMM: C[m,n] = bias1[n](+bias2[n]) + sum_k A[m,k]*W[n, woff+k] ----------------
// A: M x K row-major (lda=K). W rows: ldw stride, column offset woff. 128x128 blocktile, 8x8/thread.
__global__ void __launch_bounds__(256) sgemm_bias_kernel(
    const float* __restrict__ A, int K,
    const float* __restrict__ W, int ldw, int woff,
    const float* __restrict__ b1, const float* __restrict__ b2,
    float* __restrict__ C, int M, int N)
{
    __shared__ float As[8][128];
    __shared__ float Bs[8][128];
    const int bm = blockIdx.y * 128;
    const int bn = blockIdx.x * 128;
    const int t  = threadIdx.x;
    const int tr = (t >> 4) * 8;      // 0..120, m-offset within tile
    const int tc = (t & 15) * 8;      // 0..120, n-offset within tile
    const int lr = t >> 1;            // 0..127
    const int lc = (t & 1) * 4;       // 0 or 4

    float acc[8][8];
    #pragma unroll
    for (int i = 0; i < 8; i++)
        #pragma unroll
        for (int j = 0; j < 8; j++) acc[i][j] = 0.f;

    const bool aValid = (bm + lr) < M;     // N is always a multiple of 128 here
    const float* aRow = A + (size_t)(bm + lr) * K + lc;
    const float* wRow = W + (size_t)(bn + lr) * ldw + woff + lc;

    for (int k0 = 0; k0 < K; k0 += 8) {
        float4 av = aValid ? *(const float4*)(aRow + k0) : make_float4(0.f, 0.f, 0.f, 0.f);
        float4 wv = *(const float4*)(wRow + k0);
        As[lc + 0][lr] = av.x; As[lc + 1][lr] = av.y; As[lc + 2][lr] = av.z; As[lc + 3][lr] = av.w;
        Bs[lc + 0][lr] = wv.x; Bs[lc + 1][lr] = wv.y; Bs[lc + 2][lr] = wv.z; Bs[lc + 3][lr] = wv.w;
        __syncthreads();
        #pragma unroll
        for (int kk = 0; kk < 8; kk++) {
            float a[8], bb[8];
            *(float4*)(a)      = *(const float4*)&As[kk][tr];
            *(float4*)(a + 4)  = *(const float4*)&As[kk][tr + 4];
            *(float4*)(bb)     = *(const float4*)&Bs[kk][tc];
            *(float4*)(bb + 4) = *(const float4*)&Bs[kk][tc + 4];
            #pragma unroll
            for (int i = 0; i < 8; i++)
                #pragma unroll
                for (int j = 0; j < 8; j++) acc[i][j] += a[i] * bb[j];
        }
        __syncthreads();
    }

    float bias[8];
    #pragma unroll
    for (int j = 0; j < 8; j++) {
        int n = bn + tc + j;
        bias[j] = b1[n] + (b2 ? b2[n] : 0.f);
    }
    #pragma unroll
    for (int i = 0; i < 8; i++) {
        int m = bm + tr + i;
        if (m >= M) break;
        float* cp = C + (size_t)m * N + bn + tc;
        #pragma unroll
        for (int j = 0; j < 8; j++) cp[j] = acc[i][j] + bias[j];
    }
}

// ---------------- encoder recurrent step ----------------
// grid (32 hGroups of 16, 4 bGroups of 8), 256 threads
__global__ void __launch_bounds__(256) enc_step_kernel(
    const float* __restrict__ Whh,
    const float* __restrict__ h_in, float* __restrict__ h_out, int s)
{
    __shared__ float h_s[8][Hd];
    __shared__ float gates_s[512];
    const int hG = blockIdx.x, bG = blockIdx.y;
    const int t = threadIdx.x;

    for (int i = t; i < 8 * Hd; i += 256) {
        int bl = i >> 9, k = i & (Hd - 1);
        h_s[bl][k] = h_in[(bG * 8 + bl) * Hd + k];
    }
    __syncthreads();

    const int jl = t & 63;             // gate*16 + hoff
    const int bl0 = t >> 6;            // 0..3
    const int gate = jl >> 4, hoff = jl & 15;
    const int j = gate * Hd + hG * 16 + hoff;
    const int b0 = bG * 8 + bl0, b1i = b0 + 4;
    const float4* wv = (const float4*)(Whh + (size_t)j * Hd);

    float acc0 = g_enc_xg[((size_t)s * Bsz + b0)  * FH + j];
    float acc1 = g_enc_xg[((size_t)s * Bsz + b1i) * FH + j];
    #pragma unroll 4
    for (int k4 = 0; k4 < Hd / 4; k4++) {
        float4 w = wv[k4];
        float4 h0 = *(const float4*)&h_s[bl0][k4 * 4];
        float4 h1 = *(const float4*)&h_s[bl0 + 4][k4 * 4];
        acc0 += h0.x * w.x + h0.y * w.y + h0.z * w.z + h0.w * w.w;
        acc1 += h1.x * w.x + h1.y * w.y + h1.z * w.z + h1.w * w.w;
    }
    gates_s[bl0 * 64 + jl] = acc0;
    gates_s[(bl0 + 4) * 64 + jl] = acc1;
    __syncthreads();

    if (t < 128) {
        int bl = t >> 4, ho = t & 15;
        float ig = gates_s[bl * 64 + 0  + ho];
        float fg = gates_s[bl * 64 + 16 + ho];
        float gg = gates_s[bl * 64 + 32 + ho];
        float og = gates_s[bl * 64 + 48 + ho];
        int b = bG * 8 + bl, h = hG * 16 + ho;
        float cv = sigf(fg) * g_c[b * Hd + h] + sigf(ig) * tanhf(gg);
        float hn = sigf(og) * tanhf(cv);
        g_c[b * Hd + h] = cv;
        h_out[b * Hd + h] = hn;
        g_enc_out[((size_t)b * Ssz + s) * Hd + h] = hn;
    }
}

// ---------------- attention (one block per batch element) ----------------
__global__ void __launch_bounds__(256) attn_kernel(
    const float* __restrict__ h_in,
    const float* __restrict__ attn_W,
    const float* __restrict__ attn_v)
{
    const int b = blockIdx.x;
    const int t = threadIdx.x;
    __shared__ float h_s[Hd];
    __shared__ float v_s[Hd];
    __shared__ float hp_s[Hd];
    __shared__ float w_s[Ssz];

    for (int i = t; i < Hd; i += 256) { h_s[i] = h_in[b * Hd + i]; v_s[i] = attn_v[i]; }
    __syncthreads();

    // hproj = h @ W_h.T  (W_h = attn_W[:, :H], row stride 2H)
    for (int kk = t; kk < Hd; kk += 256) {
        const float4* wr = (const float4*)(attn_W + (size_t)kk * (2 * Hd));
        float acc = 0.f;
        #pragma unroll 4
        for (int k4 = 0; k4 < Hd / 4; k4++) {
            float4 w = wr[k4];
            float4 hh = *(const float4*)&h_s[k4 * 4];
            acc += hh.x * w.x + hh.y * w.y + hh.z * w.z + hh.w * w.w;
        }
        hp_s[kk] = acc;
    }
    __syncthreads();

    // scores[s] = sum_k tanh(hproj[k] + enc_proj[b,s,k]) * v[k]
    const int warp = t >> 5, lane = t & 31;
    for (int s = warp; s < Ssz; s += 8) {
        const float* ep = g_enc_proj + ((size_t)b * Ssz + s) * Hd;
        float acc = 0.f;
        for (int k = lane; k < Hd; k += 32)
            acc += tanhf(hp_s[k] + ep[k]) * v_s[k];
        #pragma unroll
        for (int off = 16; off; off >>= 1) acc += __shfl_xor_sync(0xffffffffu, acc, off);
        if (!lane) w_s[s] = acc;
    }
    __syncthreads();

    // softmax over S=128 (warp 0)
    if (warp == 0) {
        float v0 = w_s[lane], v1 = w_s[lane + 32], v2 = w_s[lane + 64], v3 = w_s[lane + 96];
        float m = fmaxf(fmaxf(v0, v1), fmaxf(v2, v3));
        #pragma unroll
        for (int off = 16; off; off >>= 1) m = fmaxf(m, __shfl_xor_sync(0xffffffffu, m, off));
        float e0 = __expf(v0 - m), e1 = __expf(v1 - m), e2 = __expf(v2 - m), e3 = __expf(v3 - m);
        float sum = e0 + e1 + e2 + e3;
        #pragma unroll
        for (int off = 16; off; off >>= 1) sum += __shfl_xor_sync(0xffffffffu, sum, off);
        float inv = 1.f / sum;
        w_s[lane] = e0 * inv; w_s[lane + 32] = e1 * inv;
        w_s[lane + 64] = e2 * inv; w_s[lane + 96] = e3 * inv;
    }
    __syncthreads();

    // context[h] = sum_s w[s] * enc_out[b,s,h]
    for (int h = t; h < Hd; h += 256) {
        const float* eo = g_enc_out + (size_t)b * Ssz * Hd + h;
        float acc = 0.f;
        #pragma unroll 4
        for (int s = 0; s < Ssz; s++) acc += w_s[s] * eo[(size_t)s * Hd];
        g_ctx[b * Hd + h] = acc;
    }
}

// ---------------- decoder recurrent step ----------------
__global__ void __launch_bounds__(256) dec_step_kernel(
    const float* __restrict__ Wih,   // (4H, E+H)
    const float* __restrict__ Whh,   // (4H, H)
    const float* __restrict__ h_in, float* __restrict__ h_out, int tstep)
{
    __shared__ float h_s[8][Hd];
    __shared__ float ctx_s[8][Hd];
    __shared__ float gates_s[512];
    const int hG = blockIdx.x, bG = blockIdx.y;
    const int t = threadIdx.x;

    for (int i = t; i < 8 * Hd; i += 256) {
        int bl = i >> 9, k = i & (Hd - 1);
        h_s[bl][k]   = h_in[(bG * 8 + bl) * Hd + k];
        ctx_s[bl][k] = g_ctx[(bG * 8 + bl) * Hd + k];
    }
    __syncthreads();

    const int jl = t & 63;
    const int bl0 = t >> 6;
    const int gate = jl >> 4, hoff = jl & 15;
    const int j = gate * Hd + hG * 16 + hoff;
    const int b0 = bG * 8 + bl0, b1i = b0 + 4;
    const float4* w1v = (const float4*)(Whh + (size_t)j * Hd);
    const float4* w2v = (const float4*)(Wih + (size_t)j * (Ed + Hd) + Ed);

    float acc0 = g_dec_xg[((size_t)tstep * Bsz + b0)  * FH + j];
    float acc1 = g_dec_xg[((size_t)tstep * Bsz + b1i) * FH + j];
    #pragma unroll 4
    for (int k4 = 0; k4 < Hd / 4; k4++) {
        float4 wa = w1v[k4];
        float4 wb = w2v[k4];
        float4 h0 = *(const float4*)&h_s[bl0][k4 * 4];
        float4 h1 = *(const float4*)&h_s[bl0 + 4][k4 * 4];
        float4 c0 = *(const float4*)&ctx_s[bl0][k4 * 4];
        float4 c1 = *(const float4*)&ctx_s[bl0 + 4][k4 * 4];
        acc0 += h0.x * wa.x + h0.y * wa.y + h0.z * wa.z + h0.w * wa.w;
        acc0 += c0.x * wb.x + c0.y * wb.y + c0.z * wb.z + c0.w * wb.w;
        acc1 += h1.x * wa.x + h1.y * wa.y + h1.z * wa.z + h1.w * wa.w;
        acc1 += c1.x * wb.x + c1.y * wb.y + c1.z * wb.z + c1.w * wb.w;
    }
    gates_s[bl0 * 64 + jl] = acc0;
    gates_s[(bl0 + 4) * 64 + jl] = acc1;
    __syncthreads();

    if (t < 128) {
        int bl = t >> 4, ho = t & 15;
        float ig = gates_s[bl * 64 + 0  + ho];
        float fg = gates_s[bl * 64 + 16 + ho];
        float gg = gates_s[bl * 64 + 32 + ho];
        float og = gates_s[bl * 64 + 48 + ho];
        int b = bG * 8 + bl, h = hG * 16 + ho;
        float cv = sigf(fg) * g_c[b * Hd + h] + sigf(ig) * tanhf(gg);
        float hn = sigf(og) * tanhf(cv);
        g_c[b * Hd + h] = cv;
        h_out[b * Hd + h] = hn;
        g_hs[((size_t)b * T1 + tstep) * Hd + h] = hn;
    }
}

// ---------------- launch ----------------
extern "C" void kernel_launch(void* const* d_in, const int* in_sizes, int n_in,
                              void* d_out, int out_size)
{
    const int*   src     = (const int*)d_in[0];
    const int*   tgt     = (const int*)d_in[1];
    const float* embed   = (const float*)d_in[2];
    const float* enc_Wih = (const float*)d_in[3];
    const float* enc_Whh = (const float*)d_in[4];
    const float* enc_bih = (const float*)d_in[5];
    const float* enc_bhh = (const float*)d_in[6];
    const float* dec_Wih = (const float*)d_in[7];
    const float* dec_Whh = (const float*)d_in[8];
    const float* dec_bih = (const float*)d_in[9];
    const float* dec_bhh = (const float*)d_in[10];
    const float* attn_W  = (const float*)d_in[11];
    const float* attn_b  = (const float*)d_in[12];
    const float* attn_v  = (const float*)d_in[13];
    const float* fc_W    = (const float*)d_in[14];
    const float* fc_b    = (const float*)d_in[15];
    float* out = (float*)d_out;

    float *p_src_emb, *p_dec_in, *p_enc_xg, *p_dec_xg, *p_enc_out, *p_enc_proj, *p_hs, *p_hA, *p_hB;
    cudaGetSymbolAddress((void**)&p_src_emb,  g_src_emb);
    cudaGetSymbolAddress((void**)&p_dec_in,   g_dec_in);
    cudaGetSymbolAddress((void**)&p_enc_xg,   g_enc_xg);
    cudaGetSymbolAddress((void**)&p_dec_xg,   g_dec_xg);
    cudaGetSymbolAddress((void**)&p_enc_out,  g_enc_out);
    cudaGetSymbolAddress((void**)&p_enc_proj, g_enc_proj);
    cudaGetSymbolAddress((void**)&p_hs,       g_hs);
    cudaGetSymbolAddress((void**)&p_hA,       g_hA);
    cudaGetSymbolAddress((void**)&p_hB,       g_hB);

    // init h, c = 0
    init_state_kernel<<<(Bsz * Hd + 255) / 256, 256>>>();

    // embedding gathers
    gather_src_kernel<<<Ssz * Bsz, Ed>>>(src, embed);
    gather_dec_kernel<<<T1 * Bsz, Ed>>>(tgt, embed);

    // input-side gate GEMMs (hoisted out of the scans)
    {
        dim3 grid(FH / 128, (Ssz * Bsz + 127) / 128);
        sgemm_bias_kernel<<<grid, 256>>>(p_src_emb, Ed, enc_Wih, Ed, 0,
                                         enc_bih, enc_bhh, p_enc_xg, Ssz * Bsz, FH);
    }
    {
        dim3 grid(FH / 128, (T1 * Bsz + 127) / 128);
        sgemm_bias_kernel<<<grid, 256>>>(p_dec_in, Ed, dec_Wih, Ed + Hd, 0,
                                         dec_bih, dec_bhh, p_dec_xg, T1 * Bsz, FH);
    }

    // encoder scan
    float* hin = p_hA;
    float* hout = p_hB;
    for (int s = 0; s < Ssz; s++) {
        enc_step_kernel<<<dim3(Hd / 16, Bsz / 8), 256>>>(enc_Whh, hin, hout, s);
        float* tmp = hin; hin = hout; hout = tmp;
    }

    // enc_proj = enc_out @ W_e.T + attn_b   (W_e = attn_W[:, H:])
    {
        dim3 grid(Hd / 128, (Bsz * Ssz + 127) / 128);
        sgemm_bias_kernel<<<grid, 256>>>(p_enc_out, Hd, attn_W, 2 * Hd, Hd,
                                         attn_b, nullptr, p_enc_proj, Bsz * Ssz, Hd);
    }

    // decoder scan
    for (int t = 0; t < T1; t++) {
        attn_kernel<<<Bsz, 256>>>(hin, attn_W, attn_v);
        dec_step_kernel<<<dim3(Hd / 16, Bsz / 8), 256>>>(dec_Wih, dec_Whh, hin, hout, t);
        float* tmp = hin; hin = hout; hout = tmp;
    }

    // final FC: out[b,t,v] = hs[b,t,:] @ fc_W[v,:] + fc_b[v]
    {
        dim3 grid(Vsz / 128, (Bsz * T1 + 127) / 128);
        sgemm_bias_kernel<<<grid, 256>>>(p_hs, Hd, fc_W, Hd, 0,
                                         fc_b, nullptr, out, Bsz * T1, Vsz);
    }
}

// round 3
// speedup vs baseline: 2.5442x; 2.5375x over previous
#include <cuda_runtime.h>
#include <cuda_bf16.h>
#include <cstddef>

#define Bsz 32
#define Ssz 128
#define Tsz 64
#define T1  63
#define Ed  256
#define Hd  512
#define Vsz 32000
#define FH  2048
#define NBLK 128

// ---------------- device scratch ----------------
__device__ __align__(16) float g_src_emb[(size_t)Ssz * Bsz * Ed];
__device__ __align__(16) float g_dec_in [(size_t)T1  * Bsz * Ed];
__device__ __align__(16) float g_enc_xg [(size_t)Ssz * Bsz * FH];
__device__ __align__(16) float g_dec_xg [(size_t)T1  * Bsz * FH];
__device__ __align__(16) float g_enc_out[(size_t)Bsz * Ssz * Hd];
__device__ __align__(16) float g_enc_proj[(size_t)Bsz * Ssz * Hd];
__device__ __align__(16) float g_hs     [(size_t)Bsz * T1  * Hd];
__device__ __align__(16) float g_h[2][Bsz * Hd];
__device__ __align__(16) float g_c [Bsz * Hd];
__device__ __align__(16) float g_ctx[Bsz * Hd];
__device__ __align__(16) float g_hproj[Bsz * Hd];
__device__ __align__(16) float g_scores[Bsz * Ssz];
__device__ unsigned g_cnt[2];
__device__ unsigned g_gen[2];

__device__ __forceinline__ float sigf(float x) { return 1.0f / (1.0f + expf(-x)); }

// global barrier across NBLK co-resident blocks
__device__ __forceinline__ void grid_bar(int which, unsigned target) {
    __threadfence();
    __syncthreads();
    if (threadIdx.x == 0) {
        unsigned arr = atomicAdd(&g_cnt[which], 1u);
        if (arr == NBLK - 1u) {
            g_cnt[which] = 0u;
            __threadfence();
            atomicAdd(&g_gen[which], 1u);
        } else {
            while (atomicAdd(&g_gen[which], 0u) < target) { }
        }
    }
    __syncthreads();
}

__global__ void init_state_kernel() {
    int i = blockIdx.x * blockDim.x + threadIdx.x;
    if (i < Bsz * Hd) g_h[0][i] = 0.f;
    if (i < 2) { g_cnt[i] = 0u; g_gen[i] = 0u; }
}

// ---------------- embedding gathers ----------------
__global__ void gather_src_kernel(const int* __restrict__ src, const float* __restrict__ embed) {
    int row = blockIdx.x;           // s*B + b
    int s = row >> 5, b = row & 31;
    int idx = src[b * Ssz + s];
    g_src_emb[(size_t)row * Ed + threadIdx.x] = embed[(size_t)idx * Ed + threadIdx.x];
}
__global__ void gather_dec_kernel(const int* __restrict__ tgt, const float* __restrict__ embed) {
    int row = blockIdx.x;           // t*B + b
    int t = row >> 5, b = row & 31;
    int idx = tgt[b * Tsz + t];
    g_dec_in[(size_t)row * Ed + threadIdx.x] = embed[(size_t)idx * Ed + threadIdx.x];
}

// ---------------- SGEMM (near fp32 ceiling) ----------------
__global__ void __launch_bounds__(256) sgemm_bias_kernel(
    const float* __restrict__ A, int K,
    const float* __restrict__ W, int ldw, int woff,
    const float* __restrict__ b1, const float* __restrict__ b2,
    float* __restrict__ C, int M, int N)
{
    __shared__ float As[8][128];
    __shared__ float Bs[8][128];
    const int bm = blockIdx.y * 128;
    const int bn = blockIdx.x * 128;
    const int t  = threadIdx.x;
    const int tr = (t >> 4) * 8;
    const int tc = (t & 15) * 8;
    const int lr = t >> 1;
    const int lc = (t & 1) * 4;

    float acc[8][8];
    #pragma unroll
    for (int i = 0; i < 8; i++)
        #pragma unroll
        for (int j = 0; j < 8; j++) acc[i][j] = 0.f;

    const bool aValid = (bm + lr) < M;
    const float* aRow = A + (size_t)(bm + lr) * K + lc;
    const float* wRow = W + (size_t)(bn + lr) * ldw + woff + lc;

    for (int k0 = 0; k0 < K; k0 += 8) {
        float4 av = aValid ? *(const float4*)(aRow + k0) : make_float4(0.f, 0.f, 0.f, 0.f);
        float4 wv = *(const float4*)(wRow + k0);
        As[lc + 0][lr] = av.x; As[lc + 1][lr] = av.y; As[lc + 2][lr] = av.z; As[lc + 3][lr] = av.w;
        Bs[lc + 0][lr] = wv.x; Bs[lc + 1][lr] = wv.y; Bs[lc + 2][lr] = wv.z; Bs[lc + 3][lr] = wv.w;
        __syncthreads();
        #pragma unroll
        for (int kk = 0; kk < 8; kk++) {
            float a[8], bb[8];
            *(float4*)(a)      = *(const float4*)&As[kk][tr];
            *(float4*)(a + 4)  = *(const float4*)&As[kk][tr + 4];
            *(float4*)(bb)     = *(const float4*)&Bs[kk][tc];
            *(float4*)(bb + 4) = *(const float4*)&Bs[kk][tc + 4];
            #pragma unroll
            for (int i = 0; i < 8; i++)
                #pragma unroll
                for (int j = 0; j < 8; j++) acc[i][j] += a[i] * bb[j];
        }
        __syncthreads();
    }

    float bias[8];
    #pragma unroll
    for (int j = 0; j < 8; j++) {
        int n = bn + tc + j;
        bias[j] = b1[n] + (b2 ? b2[n] : 0.f);
    }
    #pragma unroll
    for (int i = 0; i < 8; i++) {
        int m = bm + tr + i;
        if (m >= M) break;
        float* cp = C + (size_t)m * N + bn + tc;
        #pragma unroll
        for (int j = 0; j < 8; j++) cp[j] = acc[i][j] + bias[j];
    }
}

// ---------------- gate partial-GEMM helper ----------------
// 16 weight rows (4 gates x 4 h) at wbase (stride 516); 32x512 x-tile at xbase (stride 516).
// Thread (jg,bg,ks): rows {jj*4+jg}, batches {bb*8+bg}, k in [ks*64, ks*64+64).
__device__ __forceinline__ void gates_partial(
    const float* sm, int wbase, int xbase, int jg, int bg, int ks, float acc[4][4])
{
    const int k0 = ks * 64;
    #pragma unroll 4
    for (int k4 = 0; k4 < 16; k4++) {
        const int k = k0 + (k4 << 2);
        float4 wv[4], hv[4];
        #pragma unroll
        for (int jj = 0; jj < 4; jj++)
            wv[jj] = *(const float4*)&sm[wbase + (jj * 4 + jg) * 516 + k];
        #pragma unroll
        for (int bb = 0; bb < 4; bb++)
            hv[bb] = *(const float4*)&sm[xbase + (bb * 8 + bg) * 516 + k];
        #pragma unroll
        for (int jj = 0; jj < 4; jj++)
            #pragma unroll
            for (int bb = 0; bb < 4; bb++)
                acc[jj][bb] += wv[jj].x * hv[bb].x + wv[jj].y * hv[bb].y
                             + wv[jj].z * hv[bb].z + wv[jj].w * hv[bb].w;
    }
}

// ---------------- persistent encoder scan ----------------
// smem floats: W 0..8256, HX 8256..24768, RD 24768..28992
#define ENC_SMEM_BYTES (28992 * 4)
__global__ void __launch_bounds__(256, 1) enc_scan_kernel(const float* __restrict__ Whh) {
    extern __shared__ float sm[];
    const int tid = threadIdx.x, hG = blockIdx.x;
    const int W0 = 0, HX = 8256, RD = 24768;

    for (int i = tid; i < 16 * 128; i += 256) {
        int r = i >> 7, k4 = i & 127;
        int j = (r >> 2) * Hd + hG * 4 + (r & 3);
        *(float4*)&sm[W0 + r * 516 + k4 * 4] = *(const float4*)&Whh[(size_t)j * Hd + k4 * 4];
    }

    float c_reg = 0.f;
    const int jg = tid & 3, bg = (tid >> 2) & 7, ks = tid >> 5;
    unsigned bgen = 0;

    for (int s = 0; s < Ssz; s++) {
        const float* hin = g_h[s & 1];
        float* hout = g_h[(s + 1) & 1];
        for (int i = tid; i < 32 * 128; i += 256) {
            int b = i >> 7, k4 = i & 127;
            *(float4*)&sm[HX + b * 516 + k4 * 4] = __ldcg((const float4*)&hin[(b << 9) + k4 * 4]);
        }
        __syncthreads();

        float acc[4][4];
        #pragma unroll
        for (int a = 0; a < 4; a++)
            #pragma unroll
            for (int b2 = 0; b2 < 4; b2++) acc[a][b2] = 0.f;
        gates_partial(sm, W0, HX, jg, bg, ks, acc);

        #pragma unroll
        for (int jj = 0; jj < 4; jj++)
            #pragma unroll
            for (int bb = 0; bb < 4; bb++)
                sm[RD + ks * 528 + (jj * 4 + jg) * 33 + bb * 8 + bg] = acc[jj][bb];
        __syncthreads();

        if (tid < 128) {
            const int hl = tid >> 5, b = tid & 31;
            float g4[4];
            #pragma unroll
            for (int gate = 0; gate < 4; gate++) {
                int r = gate * 4 + hl;
                float a = 0.f;
                #pragma unroll
                for (int q = 0; q < 8; q++) a += sm[RD + q * 528 + r * 33 + b];
                g4[gate] = a + g_enc_xg[((size_t)s * Bsz + b) * FH + gate * Hd + hG * 4 + hl];
            }
            float cv = sigf(g4[1]) * c_reg + sigf(g4[0]) * tanhf(g4[2]);
            float hn = sigf(g4[3]) * tanhf(cv);
            c_reg = cv;
            hout[(b << 9) + hG * 4 + hl] = hn;
            g_enc_out[((size_t)b * Ssz + s) * Hd + hG * 4 + hl] = hn;
        }
        bgen++;
        grid_bar(0, bgen);
    }
    if (tid < 128) {
        const int hl = tid >> 5, b = tid & 31;
        g_c[(b << 9) + hG * 4 + hl] = c_reg;
    }
}

// ---------------- persistent decoder scan (attention fused) ----------------
// smem floats: W 0..8256, WC 8256..16512, WA 16512..18576, HX 18576..35088,
//              RD 35088..39312, HP 39312..39824, VS 39824..40336, SC 40336..40464
#define DEC_SMEM_BYTES (40464 * 4)
__global__ void __launch_bounds__(256, 1) dec_scan_kernel(
    const float* __restrict__ Wih, const float* __restrict__ Whh,
    const float* __restrict__ attnW, const float* __restrict__ attnv)
{
    extern __shared__ float sm[];
    const int tid = threadIdx.x, hG = blockIdx.x;
    const int W0 = 0, WC = 8256, WA = 16512, HX = 18576, RD = 35088,
              HP = 39312, VS = 39824, SC = 40336;

    for (int i = tid; i < 16 * 128; i += 256) {
        int r = i >> 7, k4 = i & 127;
        int j = (r >> 2) * Hd + hG * 4 + (r & 3);
        *(float4*)&sm[W0 + r * 516 + k4 * 4] = *(const float4*)&Whh[(size_t)j * Hd + k4 * 4];
        *(float4*)&sm[WC + r * 516 + k4 * 4] = *(const float4*)&Wih[(size_t)j * (Ed + Hd) + Ed + k4 * 4];
    }
    for (int i = tid; i < 4 * 128; i += 256) {
        int r = i >> 7, k4 = i & 127;
        *(float4*)&sm[WA + r * 516 + k4 * 4] = *(const float4*)&attnW[(size_t)(hG * 4 + r) * (2 * Hd) + k4 * 4];
    }
    for (int i = tid; i < Hd; i += 256) sm[VS + i] = attnv[i];

    float c_reg = 0.f;
    if (tid < 128) {
        const int hl = tid >> 5, b = tid & 31;
        c_reg = __ldcg(&g_c[(b << 9) + hG * 4 + hl]);
    }

    const int jg = tid & 3, bg = (tid >> 2) & 7, ks = tid >> 5;
    const int bB = hG >> 2;
    unsigned bgen = 0;

    for (int t = 0; t < T1; t++) {
        const float* hin = g_h[t & 1];
        float* hout = g_h[(t + 1) & 1];

        // ---- phase A: load h, hproj, h-part gate partials ----
        for (int i = tid; i < 32 * 128; i += 256) {
            int b = i >> 7, k4 = i & 127;
            *(float4*)&sm[HX + b * 516 + k4 * 4] = __ldcg((const float4*)&hin[(b << 9) + k4 * 4]);
        }
        __syncthreads();
        {
            const int ko = tid >> 6, bh = (tid >> 1) & 31, kh = tid & 1;
            float a = 0.f;
            const int kb = kh << 8;
            #pragma unroll 4
            for (int k = kb; k < kb + 256; k += 4) {
                float4 w4 = *(const float4*)&sm[WA + ko * 516 + k];
                float4 h4 = *(const float4*)&sm[HX + bh * 516 + k];
                a += w4.x * h4.x + w4.y * h4.y + w4.z * h4.z + w4.w * h4.w;
            }
            a += __shfl_xor_sync(0xffffffffu, a, 1);
            if (!kh) g_hproj[(bh << 9) + hG * 4 + ko] = a;
        }
        float acc[4][4];
        #pragma unroll
        for (int a2 = 0; a2 < 4; a2++)
            #pragma unroll
            for (int b2 = 0; b2 < 4; b2++) acc[a2][b2] = 0.f;
        gates_partial(sm, W0, HX, jg, bg, ks, acc);
        bgen++; grid_bar(1, bgen);

        // ---- phase B: scores for (bB, s0..s0+31) ----
        for (int i = tid; i < Hd; i += 256) sm[HP + i] = __ldcg(&g_hproj[(bB << 9) + i]);
        __syncthreads();
        {
            const int s0 = (hG & 3) * 32, w = tid >> 5, lane = tid & 31;
            #pragma unroll
            for (int q = 0; q < 4; q++) {
                int s2 = s0 + w * 4 + q;
                const float* ep = g_enc_proj + ((size_t)bB * Ssz + s2) * Hd;
                float a = 0.f;
                for (int kk = lane; kk < Hd; kk += 32)
                    a += tanhf(sm[HP + kk] + ep[kk]) * sm[VS + kk];
                #pragma unroll
                for (int off = 16; off; off >>= 1) a += __shfl_xor_sync(0xffffffffu, a, off);
                if (!lane) g_scores[bB * Ssz + s2] = a;
            }
        }
        bgen++; grid_bar(1, bgen);

        // ---- phase C: softmax (redundant per block) + context slice ----
        if (tid < 128) sm[SC + tid] = __ldcg(&g_scores[bB * Ssz + tid]);
        __syncthreads();
        float m = -1e30f;
        for (int i2 = 0; i2 < 128; i2++) m = fmaxf(m, sm[SC + i2]);
        __syncthreads();
        if (tid < 128) sm[SC + tid] = expf(sm[SC + tid] - m);
        __syncthreads();
        float ssum = 0.f;
        for (int i2 = 0; i2 < 128; i2++) ssum += sm[SC + i2];
        {
            const float inv = 1.f / ssum;
            const int h0 = (hG & 3) * 128, h = h0 + (tid >> 1), sh = tid & 1;
            const float* eo = g_enc_out + ((size_t)bB * Ssz + (sh << 6)) * Hd + h;
            float a = 0.f;
            #pragma unroll 4
            for (int s2 = 0; s2 < 64; s2++) a += sm[SC + (sh << 6) + s2] * eo[(size_t)s2 * Hd];
            a += __shfl_xor_sync(0xffffffffu, a, 1);
            if (!sh) g_ctx[(bB << 9) + h] = a * inv;
        }
        bgen++; grid_bar(1, bgen);

        // ---- phase D: ctx-part gates + pointwise ----
        for (int i = tid; i < 32 * 128; i += 256) {
            int b = i >> 7, k4 = i & 127;
            *(float4*)&sm[HX + b * 516 + k4 * 4] = __ldcg((const float4*)&g_ctx[(b << 9) + k4 * 4]);
        }
        __syncthreads();
        gates_partial(sm, WC, HX, jg, bg, ks, acc);

        #pragma unroll
        for (int jj = 0; jj < 4; jj++)
            #pragma unroll
            for (int bb = 0; bb < 4; bb++)
                sm[RD + ks * 528 + (jj * 4 + jg) * 33 + bb * 8 + bg] = acc[jj][bb];
        __syncthreads();

        if (tid < 128) {
            const int hl = tid >> 5, b = tid & 31;
            float g4[4];
            #pragma unroll
            for (int gate = 0; gate < 4; gate++) {
                int r = gate * 4 + hl;
                float a = 0.f;
                #pragma unroll
                for (int q = 0; q < 8; q++) a += sm[RD + q * 528 + r * 33 + b];
                g4[gate] = a + g_dec_xg[((size_t)t * Bsz + b) * FH + gate * Hd + hG * 4 + hl];
            }
            float cv = sigf(g4[1]) * c_reg + sigf(g4[0]) * tanhf(g4[2]);
            float hn = sigf(g4[3]) * tanhf(cv);
            c_reg = cv;
            hout[(b << 9) + hG * 4 + hl] = hn;
            g_hs[((size_t)b * T1 + t) * Hd + hG * 4 + hl] = hn;
        }
        bgen++; grid_bar(1, bgen);
    }
}

// ---------------- launch ----------------
extern "C" void kernel_launch(void* const* d_in, const int* in_sizes, int n_in,
                              void* d_out, int out_size)
{
    const int*   src     = (const int*)d_in[0];
    const int*   tgt     = (const int*)d_in[1];
    const float* embed   = (const float*)d_in[2];
    const float* enc_Wih = (const float*)d_in[3];
    const float* enc_Whh = (const float*)d_in[4];
    const float* enc_bih = (const float*)d_in[5];
    const float* enc_bhh = (const float*)d_in[6];
    const float* dec_Wih = (const float*)d_in[7];
    const float* dec_Whh = (const float*)d_in[8];
    const float* dec_bih = (const float*)d_in[9];
    const float* dec_bhh = (const float*)d_in[10];
    const float* attn_W  = (const float*)d_in[11];
    const float* attn_b  = (const float*)d_in[12];
    const float* attn_v  = (const float*)d_in[13];
    const float* fc_W    = (const float*)d_in[14];
    const float* fc_b    = (const float*)d_in[15];
    float* out = (float*)d_out;

    float *p_src_emb, *p_dec_in, *p_enc_xg, *p_dec_xg, *p_enc_out, *p_enc_proj, *p_hs;
    cudaGetSymbolAddress((void**)&p_src_emb,  g_src_emb);
    cudaGetSymbolAddress((void**)&p_dec_in,   g_dec_in);
    cudaGetSymbolAddress((void**)&p_enc_xg,   g_enc_xg);
    cudaGetSymbolAddress((void**)&p_dec_xg,   g_dec_xg);
    cudaGetSymbolAddress((void**)&p_enc_out,  g_enc_out);
    cudaGetSymbolAddress((void**)&p_enc_proj, g_enc_proj);
    cudaGetSymbolAddress((void**)&p_hs,       g_hs);

    cudaFuncSetAttribute(enc_scan_kernel, cudaFuncAttributeMaxDynamicSharedMemorySize, ENC_SMEM_BYTES);
    cudaFuncSetAttribute(dec_scan_kernel, cudaFuncAttributeMaxDynamicSharedMemorySize, DEC_SMEM_BYTES);

    init_state_kernel<<<(Bsz * Hd + 255) / 256, 256>>>();
    gather_src_kernel<<<Ssz * Bsz, Ed>>>(src, embed);
    gather_dec_kernel<<<T1 * Bsz, Ed>>>(tgt, embed);

    {   // enc_xg = src_emb @ enc_Wih.T + biases
        dim3 grid(FH / 128, (Ssz * Bsz + 127) / 128);
        sgemm_bias_kernel<<<grid, 256>>>(p_src_emb, Ed, enc_Wih, Ed, 0,
                                         enc_bih, enc_bhh, p_enc_xg, Ssz * Bsz, FH);
    }
    {   // dec_xg = dec_in @ dec_Wih[:, :E].T + biases
        dim3 grid(FH / 128, (T1 * Bsz + 127) / 128);
        sgemm_bias_kernel<<<grid, 256>>>(p_dec_in, Ed, dec_Wih, Ed + Hd, 0,
                                         dec_bih, dec_bhh, p_dec_xg, T1 * Bsz, FH);
    }

    // persistent encoder scan (128 steps, 1 kernel)
    enc_scan_kernel<<<NBLK, 256, ENC_SMEM_BYTES>>>(enc_Whh);

    {   // enc_proj = enc_out @ W_e.T + attn_b
        dim3 grid(Hd / 128, (Bsz * Ssz + 127) / 128);
        sgemm_bias_kernel<<<grid, 256>>>(p_enc_out, Hd, attn_W, 2 * Hd, Hd,
                                         attn_b, nullptr, p_enc_proj, Bsz * Ssz, Hd);
    }

    // persistent decoder scan (63 steps, attention fused, 1 kernel)
    dec_scan_kernel<<<NBLK, 256, DEC_SMEM_BYTES>>>(dec_Wih, dec_Whh, attn_W, attn_v);

    {   // final FC
        dim3 grid(Vsz / 128, (Bsz * T1 + 127) / 128);
        sgemm_bias_kernel<<<grid, 256>>>(p_hs, Hd, fc_W, Hd, 0,
                                         fc_b, nullptr, out, Bsz * T1, Vsz);
    }
}

// round 6
// speedup vs baseline: 3.3403x; 1.3129x over previous
#include <cuda_runtime.h>
#include <cuda_bf16.h>
#include <cstddef>
#include <cstdint>

#define Bsz 32
#define Ssz 128
#define Tsz 64
#define T1  63
#define Ed  256
#define Hd  512
#define Vsz 32000
#define FH  2048
#define NBLK 128
#define Mrows 2016       // Bsz*T1
#define MrowsPad 2048

// ---------------- device scratch ----------------
__device__ __align__(16) float g_src_emb[(size_t)Ssz * Bsz * Ed];
__device__ __align__(16) float g_dec_in [(size_t)T1  * Bsz * Ed];
__device__ __align__(16) float g_enc_xg [(size_t)Ssz * Bsz * FH];
__device__ __align__(16) float g_dec_xg [(size_t)T1  * Bsz * FH];
__device__ __align__(16) float g_enc_out[(size_t)Bsz * Ssz * Hd];
__device__ __align__(16) float g_enc_proj[(size_t)Bsz * Ssz * Hd];
__device__ __align__(16) float g_hs     [(size_t)Bsz * T1  * Hd];
__device__ __align__(16) float g_h[2][Bsz * Hd];
__device__ __align__(16) float g_c [Bsz * Hd];
__device__ __align__(16) float g_ctx[Bsz * Hd];
__device__ __align__(16) float g_hproj[Bsz * Hd];
__device__ __align__(16) float g_scores[Bsz * Ssz];
__device__ unsigned g_cnt[2];
__device__ unsigned g_gen[2];
// bf16 hi/lo split operands for the FC tensor GEMM
__device__ __align__(16) __nv_bfloat16 g_hs_hi[(size_t)MrowsPad * Hd];
__device__ __align__(16) __nv_bfloat16 g_hs_lo[(size_t)MrowsPad * Hd];
__device__ __align__(16) __nv_bfloat16 g_fcw_hi[(size_t)Vsz * Hd];
__device__ __align__(16) __nv_bfloat16 g_fcw_lo[(size_t)Vsz * Hd];

__device__ __forceinline__ float sigf(float x) { return 1.0f / (1.0f + expf(-x)); }

__device__ __forceinline__ uint32_t smem_to_u32(const void* p) {
    uint32_t a;
    asm("{ .reg .u64 t; cvta.to.shared.u64 t, %1; cvt.u32.u64 %0, t; }" : "=r"(a) : "l"(p));
    return a;
}
__device__ __forceinline__ void ldsm_x4(uint32_t* r, uint32_t addr) {
    asm volatile("ldmatrix.sync.aligned.m8n8.x4.shared.b16 {%0,%1,%2,%3}, [%4];"
        : "=r"(r[0]), "=r"(r[1]), "=r"(r[2]), "=r"(r[3]) : "r"(addr));
}
__device__ __forceinline__ void mma_bf16(float* d, const uint32_t* a, uint32_t b0, uint32_t b1) {
    asm volatile("mma.sync.aligned.m16n8k16.row.col.f32.bf16.bf16.f32 "
        "{%0,%1,%2,%3}, {%4,%5,%6,%7}, {%8,%9}, {%0,%1,%2,%3};"
        : "+f"(d[0]), "+f"(d[1]), "+f"(d[2]), "+f"(d[3])
        : "r"(a[0]), "r"(a[1]), "r"(a[2]), "r"(a[3]), "r"(b0), "r"(b1));
}

// ---------------- global barrier across NBLK co-resident blocks ----------------
__device__ __forceinline__ void grid_bar(int which, unsigned target) {
    __threadfence();
    __syncthreads();
    if (threadIdx.x == 0) {
        unsigned arr = atomicAdd(&g_cnt[which], 1u);
        if (arr == NBLK - 1u) {
            g_cnt[which] = 0u;
            __threadfence();
            atomicAdd(&g_gen[which], 1u);
        } else {
            while (atomicAdd(&g_gen[which], 0u) < target) { }
        }
    }
    __syncthreads();
}

__global__ void init_state_kernel() {
    int i = blockIdx.x * blockDim.x + threadIdx.x;
    if (i < Bsz * Hd) g_h[0][i] = 0.f;
    if (i < 2) { g_cnt[i] = 0u; g_gen[i] = 0u; }
}

// ---------------- embedding gathers ----------------
__global__ void gather_src_kernel(const int* __restrict__ src, const float* __restrict__ embed) {
    int row = blockIdx.x;           // s*B + b
    int s = row >> 5, b = row & 31;
    int idx = src[b * Ssz + s];
    g_src_emb[(size_t)row * Ed + threadIdx.x] = embed[(size_t)idx * Ed + threadIdx.x];
}
__global__ void gather_dec_kernel(const int* __restrict__ tgt, const float* __restrict__ embed) {
    int row = blockIdx.x;           // t*B + b
    int t = row >> 5, b = row & 31;
    int idx = tgt[b * Tsz + t];
    g_dec_in[(size_t)row * Ed + threadIdx.x] = embed[(size_t)idx * Ed + threadIdx.x];
}

// ---------------- fp32 SGEMM (small GEMMs) ----------------
__global__ void __launch_bounds__(256) sgemm_bias_kernel(
    const float* __restrict__ A, int K,
    const float* __restrict__ W, int ldw, int woff,
    const float* __restrict__ b1, const float* __restrict__ b2,
    float* __restrict__ C, int M, int N)
{
    __shared__ float As[8][128];
    __shared__ float Bs[8][128];
    const int bm = blockIdx.y * 128;
    const int bn = blockIdx.x * 128;
    const int t  = threadIdx.x;
    const int tr = (t >> 4) * 8;
    const int tc = (t & 15) * 8;
    const int lr = t >> 1;
    const int lc = (t & 1) * 4;

    float acc[8][8];
    #pragma unroll
    for (int i = 0; i < 8; i++)
        #pragma unroll
        for (int j = 0; j < 8; j++) acc[i][j] = 0.f;

    const bool aValid = (bm + lr) < M;
    const float* aRow = A + (size_t)(bm + lr) * K + lc;
    const float* wRow = W + (size_t)(bn + lr) * ldw + woff + lc;

    for (int k0 = 0; k0 < K; k0 += 8) {
        float4 av = aValid ? *(const float4*)(aRow + k0) : make_float4(0.f, 0.f, 0.f, 0.f);
        float4 wv = *(const float4*)(wRow + k0);
        As[lc + 0][lr] = av.x; As[lc + 1][lr] = av.y; As[lc + 2][lr] = av.z; As[lc + 3][lr] = av.w;
        Bs[lc + 0][lr] = wv.x; Bs[lc + 1][lr] = wv.y; Bs[lc + 2][lr] = wv.z; Bs[lc + 3][lr] = wv.w;
        __syncthreads();
        #pragma unroll
        for (int kk = 0; kk < 8; kk++) {
            float a[8], bb[8];
            *(float4*)(a)      = *(const float4*)&As[kk][tr];
            *(float4*)(a + 4)  = *(const float4*)&As[kk][tr + 4];
            *(float4*)(bb)     = *(const float4*)&Bs[kk][tc];
            *(float4*)(bb + 4) = *(const float4*)&Bs[kk][tc + 4];
            #pragma unroll
            for (int i = 0; i < 8; i++)
                #pragma unroll
                for (int j = 0; j < 8; j++) acc[i][j] += a[i] * bb[j];
        }
        __syncthreads();
    }

    float bias[8];
    #pragma unroll
    for (int j = 0; j < 8; j++) {
        int n = bn + tc + j;
        bias[j] = b1[n] + (b2 ? b2[n] : 0.f);
    }
    #pragma unroll
    for (int i = 0; i < 8; i++) {
        int m = bm + tr + i;
        if (m >= M) break;
        float* cp = C + (size_t)m * N + bn + tc;
        #pragma unroll
        for (int j = 0; j < 8; j++) cp[j] = acc[i][j] + bias[j];
    }
}

// ---------------- gate partial-GEMM helper ----------------
__device__ __forceinline__ void gates_partial(
    const float* sm, int wbase, int xbase, int jg, int bg, int ks, float acc[4][4])
{
    const int k0 = ks * 64;
    #pragma unroll 4
    for (int k4 = 0; k4 < 16; k4++) {
        const int k = k0 + (k4 << 2);
        float4 wv[4], hv[4];
        #pragma unroll
        for (int jj = 0; jj < 4; jj++)
            wv[jj] = *(const float4*)&sm[wbase + (jj * 4 + jg) * 516 + k];
        #pragma unroll
        for (int bb = 0; bb < 4; bb++)
            hv[bb] = *(const float4*)&sm[xbase + (bb * 8 + bg) * 516 + k];
        #pragma unroll
        for (int jj = 0; jj < 4; jj++)
            #pragma unroll
            for (int bb = 0; bb < 4; bb++)
                acc[jj][bb] += wv[jj].x * hv[bb].x + wv[jj].y * hv[bb].y
                             + wv[jj].z * hv[bb].z + wv[jj].w * hv[bb].w;
    }
}

// ---------------- persistent encoder scan ----------------
#define ENC_SMEM_BYTES (28992 * 4)
__global__ void __launch_bounds__(256, 1) enc_scan_kernel(const float* __restrict__ Whh) {
    extern __shared__ float sm[];
    const int tid = threadIdx.x, hG = blockIdx.x;
    const int W0 = 0, HX = 8256, RD = 24768;

    for (int i = tid; i < 16 * 128; i += 256) {
        int r = i >> 7, k4 = i & 127;
        int j = (r >> 2) * Hd + hG * 4 + (r & 3);
        *(float4*)&sm[W0 + r * 516 + k4 * 4] = *(const float4*)&Whh[(size_t)j * Hd + k4 * 4];
    }

    float c_reg = 0.f;
    const int jg = tid & 3, bg = (tid >> 2) & 7, ks = tid >> 5;
    unsigned bgen = 0;

    for (int s = 0; s < Ssz; s++) {
        const float* hin = g_h[s & 1];
        float* hout = g_h[(s + 1) & 1];
        for (int i = tid; i < 32 * 128; i += 256) {
            int b = i >> 7, k4 = i & 127;
            *(float4*)&sm[HX + b * 516 + k4 * 4] = __ldcg((const float4*)&hin[(b << 9) + k4 * 4]);
        }
        __syncthreads();

        float acc[4][4];
        #pragma unroll
        for (int a = 0; a < 4; a++)
            #pragma unroll
            for (int b2 = 0; b2 < 4; b2++) acc[a][b2] = 0.f;
        gates_partial(sm, W0, HX, jg, bg, ks, acc);

        #pragma unroll
        for (int jj = 0; jj < 4; jj++)
            #pragma unroll
            for (int bb = 0; bb < 4; bb++)
                sm[RD + ks * 528 + (jj * 4 + jg) * 33 + bb * 8 + bg] = acc[jj][bb];
        __syncthreads();

        if (tid < 128) {
            const int hl = tid >> 5, b = tid & 31;
            float g4[4];
            #pragma unroll
            for (int gate = 0; gate < 4; gate++) {
                int r = gate * 4 + hl;
                float a = 0.f;
                #pragma unroll
                for (int q = 0; q < 8; q++) a += sm[RD + q * 528 + r * 33 + b];
                g4[gate] = a + g_enc_xg[((size_t)s * Bsz + b) * FH + gate * Hd + hG * 4 + hl];
            }
            float cv = sigf(g4[1]) * c_reg + sigf(g4[0]) * tanhf(g4[2]);
            float hn = sigf(g4[3]) * tanhf(cv);
            c_reg = cv;
            hout[(b << 9) + hG * 4 + hl] = hn;
            g_enc_out[((size_t)b * Ssz + s) * Hd + hG * 4 + hl] = hn;
        }
        bgen++;
        grid_bar(0, bgen);
    }
    if (tid < 128) {
        const int hl = tid >> 5, b = tid & 31;
        g_c[(b << 9) + hG * 4 + hl] = c_reg;
    }
}

// ---------------- persistent decoder scan (attention fused) ----------------
#define DEC_SMEM_BYTES (40464 * 4)
__global__ void __launch_bounds__(256, 1) dec_scan_kernel(
    const float* __restrict__ Wih, const float* __restrict__ Whh,
    const float* __restrict__ attnW, const float* __restrict__ attnv)
{
    extern __shared__ float sm[];
    const int tid = threadIdx.x, hG = blockIdx.x;
    const int W0 = 0, WC = 8256, WA = 16512, HX = 18576, RD = 35088,
              HP = 39312, VS = 39824, SC = 40336;

    for (int i = tid; i < 16 * 128; i += 256) {
        int r = i >> 7, k4 = i & 127;
        int j = (r >> 2) * Hd + hG * 4 + (r & 3);
        *(float4*)&sm[W0 + r * 516 + k4 * 4] = *(const float4*)&Whh[(size_t)j * Hd + k4 * 4];
        *(float4*)&sm[WC + r * 516 + k4 * 4] = *(const float4*)&Wih[(size_t)j * (Ed + Hd) + Ed + k4 * 4];
    }
    for (int i = tid; i < 4 * 128; i += 256) {
        int r = i >> 7, k4 = i & 127;
        *(float4*)&sm[WA + r * 516 + k4 * 4] = *(const float4*)&attnW[(size_t)(hG * 4 + r) * (2 * Hd) + k4 * 4];
    }
    for (int i = tid; i < Hd; i += 256) sm[VS + i] = attnv[i];

    float c_reg = 0.f;
    if (tid < 128) {
        const int hl = tid >> 5, b = tid & 31;
        c_reg = __ldcg(&g_c[(b << 9) + hG * 4 + hl]);
    }

    const int jg = tid & 3, bg = (tid >> 2) & 7, ks = tid >> 5;
    const int bB = hG >> 2;
    unsigned bgen = 0;

    for (int t = 0; t < T1; t++) {
        const float* hin = g_h[t & 1];
        float* hout = g_h[(t + 1) & 1];

        // ---- phase A ----
        for (int i = tid; i < 32 * 128; i += 256) {
            int b = i >> 7, k4 = i & 127;
            *(float4*)&sm[HX + b * 516 + k4 * 4] = __ldcg((const float4*)&hin[(b << 9) + k4 * 4]);
        }
        __syncthreads();
        {
            const int ko = tid >> 6, bh = (tid >> 1) & 31, kh = tid & 1;
            float a = 0.f;
            const int kb = kh << 8;
            #pragma unroll 4
            for (int k = kb; k < kb + 256; k += 4) {
                float4 w4 = *(const float4*)&sm[WA + ko * 516 + k];
                float4 h4 = *(const float4*)&sm[HX + bh * 516 + k];
                a += w4.x * h4.x + w4.y * h4.y + w4.z * h4.z + w4.w * h4.w;
            }
            a += __shfl_xor_sync(0xffffffffu, a, 1);
            if (!kh) g_hproj[(bh << 9) + hG * 4 + ko] = a;
        }
        float acc[4][4];
        #pragma unroll
        for (int a2 = 0; a2 < 4; a2++)
            #pragma unroll
            for (int b2 = 0; b2 < 4; b2++) acc[a2][b2] = 0.f;
        gates_partial(sm, W0, HX, jg, bg, ks, acc);
        bgen++; grid_bar(1, bgen);

        // ---- phase B ----
        for (int i = tid; i < Hd; i += 256) sm[HP + i] = __ldcg(&g_hproj[(bB << 9) + i]);
        __syncthreads();
        {
            const int s0 = (hG & 3) * 32, w = tid >> 5, lane = tid & 31;
            #pragma unroll
            for (int q = 0; q < 4; q++) {
                int s2 = s0 + w * 4 + q;
                const float* ep = g_enc_proj + ((size_t)bB * Ssz + s2) * Hd;
                float a = 0.f;
                for (int kk = lane; kk < Hd; kk += 32)
                    a += tanhf(sm[HP + kk] + ep[kk]) * sm[VS + kk];
                #pragma unroll
                for (int off = 16; off; off >>= 1) a += __shfl_xor_sync(0xffffffffu, a, off);
                if (!lane) g_scores[bB * Ssz + s2] = a;
            }
        }
        bgen++; grid_bar(1, bgen);

        // ---- phase C ----
        if (tid < 128) sm[SC + tid] = __ldcg(&g_scores[bB * Ssz + tid]);
        __syncthreads();
        float m = -1e30f;
        for (int i2 = 0; i2 < 128; i2++) m = fmaxf(m, sm[SC + i2]);
        __syncthreads();
        if (tid < 128) sm[SC + tid] = expf(sm[SC + tid] - m);
        __syncthreads();
        float ssum = 0.f;
        for (int i2 = 0; i2 < 128; i2++) ssum += sm[SC + i2];
        {
            const float inv = 1.f / ssum;
            const int h0 = (hG & 3) * 128, h = h0 + (tid >> 1), sh = tid & 1;
            const float* eo = g_enc_out + ((size_t)bB * Ssz + (sh << 6)) * Hd + h;
            float a = 0.f;
            #pragma unroll 4
            for (int s2 = 0; s2 < 64; s2++) a += sm[SC + (sh << 6) + s2] * eo[(size_t)s2 * Hd];
            a += __shfl_xor_sync(0xffffffffu, a, 1);
            if (!sh) g_ctx[(bB << 9) + h] = a * inv;
        }
        bgen++; grid_bar(1, bgen);

        // ---- phase D ----
        for (int i = tid; i < 32 * 128; i += 256) {
            int b = i >> 7, k4 = i & 127;
            *(float4*)&sm[HX + b * 516 + k4 * 4] = __ldcg((const float4*)&g_ctx[(b << 9) + k4 * 4]);
        }
        __syncthreads();
        gates_partial(sm, WC, HX, jg, bg, ks, acc);

        #pragma unroll
        for (int jj = 0; jj < 4; jj++)
            #pragma unroll
            for (int bb = 0; bb < 4; bb++)
                sm[RD + ks * 528 + (jj * 4 + jg) * 33 + bb * 8 + bg] = acc[jj][bb];
        __syncthreads();

        if (tid < 128) {
            const int hl = tid >> 5, b = tid & 31;
            float g4[4];
            #pragma unroll
            for (int gate = 0; gate < 4; gate++) {
                int r = gate * 4 + hl;
                float a = 0.f;
                #pragma unroll
                for (int q = 0; q < 8; q++) a += sm[RD + q * 528 + r * 33 + b];
                g4[gate] = a + g_dec_xg[((size_t)t * Bsz + b) * FH + gate * Hd + hG * 4 + hl];
            }
            float cv = sigf(g4[1]) * c_reg + sigf(g4[0]) * tanhf(g4[2]);
            float hn = sigf(g4[3]) * tanhf(cv);
            c_reg = cv;
            hout[(b << 9) + hG * 4 + hl] = hn;
            g_hs[((size_t)b * T1 + t) * Hd + hG * 4 + hl] = hn;
        }
        bgen++; grid_bar(1, bgen);
    }
}

// ---------------- bf16 hi/lo split conversions ----------------
__global__ void conv_hs_kernel() {
    size_t i = ((size_t)blockIdx.x * 256 + threadIdx.x) * 4;
    if (i >= (size_t)MrowsPad * Hd) return;
    float4 x = (i < (size_t)Mrows * Hd) ? *(const float4*)&g_hs[i] : make_float4(0.f, 0.f, 0.f, 0.f);
    float v[4] = {x.x, x.y, x.z, x.w};
    #pragma unroll
    for (int j = 0; j < 4; j++) {
        __nv_bfloat16 hi = __float2bfloat16(v[j]);
        g_hs_hi[i + j] = hi;
        g_hs_lo[i + j] = __float2bfloat16(v[j] - __bfloat162float(hi));
    }
}
__global__ void conv_w_kernel(const float* __restrict__ fc_W) {
    size_t i = ((size_t)blockIdx.x * 256 + threadIdx.x) * 4;
    if (i >= (size_t)Vsz * Hd) return;
    float4 x = *(const float4*)&fc_W[i];
    float v[4] = {x.x, x.y, x.z, x.w};
    #pragma unroll
    for (int j = 0; j < 4; j++) {
        __nv_bfloat16 hi = __float2bfloat16(v[j]);
        g_fcw_hi[i + j] = hi;
        g_fcw_lo[i + j] = __float2bfloat16(v[j] - __bfloat162float(hi));
    }
}

// ---------------- FC GEMM via mma.sync bf16 (hi/lo split) ----------------
// CTA: 128x128 tile. 8 warps = 4(m) x 2(n); warp tile 32x64 (2 m16 x 8 n8).
// K=512 in 8 chunks of 64. smem tiles 128x64 bf16 at stride 72.
// Both A (m-major, k contig) and B (n-major, k contig) use NON-trans ldmatrix:
// plain ldmatrix on an n-row/k-col tile yields exactly the row.col B fragment.
#define FC_TS 9216                   // bf16 elems per tile (128*72)
#define FC_SMEM_BYTES (4 * FC_TS * 2)   // 73728
__global__ void __launch_bounds__(256, 1) fc_mma_kernel(
    const float* __restrict__ fc_b, float* __restrict__ out)
{
    extern __shared__ __nv_bfloat16 smb[];
    const int tid = threadIdx.x, lane = tid & 31, wid = tid >> 5;
    const int wm = wid & 3, wn = wid >> 2;
    const int m0 = blockIdx.x * 128, n0 = blockIdx.y * 128;
    const uint32_t smem_base = smem_to_u32(smb);

    const __nv_bfloat16* Ah = g_hs_hi  + (size_t)m0 * Hd;
    const __nv_bfloat16* Al = g_hs_lo  + (size_t)m0 * Hd;
    const __nv_bfloat16* Bh = g_fcw_hi + (size_t)n0 * Hd;
    const __nv_bfloat16* Bl = g_fcw_lo + (size_t)n0 * Hd;

    float acc[2][8][4];
    #pragma unroll
    for (int a = 0; a < 2; a++)
        #pragma unroll
        for (int b = 0; b < 8; b++)
            #pragma unroll
            for (int c = 0; c < 4; c++) acc[a][b][c] = 0.f;

    // ldmatrix lane addressing: row = base + ((lane>>3)&1)*8 + (lane&7), col = (lane>>4)*8
    const int lrow = ((lane >> 3) & 1) * 8 + (lane & 7);
    const int lcol = (lane >> 4) * 8;

    for (int kc = 0; kc < 8; kc++) {
        for (int i = tid; i < 1024; i += 256) {
            int r = i >> 3, c8 = i & 7;
            int dst = r * 72 + c8 * 8;
            size_t gi = (size_t)r * Hd + kc * 64 + c8 * 8;
            *(uint4*)(smb + dst)              = *(const uint4*)(Ah + gi);
            *(uint4*)(smb + FC_TS + dst)      = *(const uint4*)(Al + gi);
            *(uint4*)(smb + 2 * FC_TS + dst)  = *(const uint4*)(Bh + gi);
            *(uint4*)(smb + 3 * FC_TS + dst)  = *(const uint4*)(Bl + gi);
        }
        __syncthreads();

        #pragma unroll
        for (int kk = 0; kk < 4; kk++) {
            uint32_t ah[2][4], al[2][4], bh[4][4], bl[4][4];
            #pragma unroll
            for (int mt = 0; mt < 2; mt++) {
                uint32_t off = (uint32_t)(((wm * 32 + mt * 16 + lrow) * 72 + kk * 16 + lcol) * 2);
                ldsm_x4(ah[mt], smem_base + off);
                ldsm_x4(al[mt], smem_base + 2u * FC_TS + off);
            }
            #pragma unroll
            for (int ng = 0; ng < 4; ng++) {
                uint32_t off = (uint32_t)(((wn * 64 + ng * 16 + lrow) * 72 + kk * 16 + lcol) * 2);
                ldsm_x4(bh[ng], smem_base + 4u * FC_TS + off);
                ldsm_x4(bl[ng], smem_base + 6u * FC_TS + off);
            }
            #pragma unroll
            for (int mt = 0; mt < 2; mt++)
                #pragma unroll
                for (int ng = 0; ng < 4; ng++) {
                    // non-trans x4 on n-major tile: r0=(n0-7,k0-7), r1=(n8-15,k0-7),
                    // r2=(n0-7,k8-15), r3=(n8-15,k8-15)
                    mma_bf16(acc[mt][ng * 2],     ah[mt], bh[ng][0], bh[ng][2]);
                    mma_bf16(acc[mt][ng * 2],     ah[mt], bl[ng][0], bl[ng][2]);
                    mma_bf16(acc[mt][ng * 2],     al[mt], bh[ng][0], bh[ng][2]);
                    mma_bf16(acc[mt][ng * 2 + 1], ah[mt], bh[ng][1], bh[ng][3]);
                    mma_bf16(acc[mt][ng * 2 + 1], ah[mt], bl[ng][1], bl[ng][3]);
                    mma_bf16(acc[mt][ng * 2 + 1], al[mt], bh[ng][1], bh[ng][3]);
                }
        }
        __syncthreads();
    }

    // epilogue: d frag: (d0,d1)@row lane/4, cols (lane&3)*2..+1; (d2,d3)@row+8
    const int rbase = m0 + wm * 32 + (lane >> 2);
    const int cbase = n0 + wn * 64 + (lane & 3) * 2;
    #pragma unroll
    for (int mt = 0; mt < 2; mt++)
        #pragma unroll
        for (int nt = 0; nt < 8; nt++) {
            int c = cbase + nt * 8;
            float b0 = fc_b[c], b1 = fc_b[c + 1];
            int r0 = rbase + mt * 16;
            if (r0 < Mrows) {
                float2 v = make_float2(acc[mt][nt][0] + b0, acc[mt][nt][1] + b1);
                *(float2*)&out[(size_t)r0 * Vsz + c] = v;
            }
            int r1 = r0 + 8;
            if (r1 < Mrows) {
                float2 v = make_float2(acc[mt][nt][2] + b0, acc[mt][nt][3] + b1);
                *(float2*)&out[(size_t)r1 * Vsz + c] = v;
            }
        }
}

// ---------------- launch ----------------
extern "C" void kernel_launch(void* const* d_in, const int* in_sizes, int n_in,
                              void* d_out, int out_size)
{
    const int*   src     = (const int*)d_in[0];
    const int*   tgt     = (const int*)d_in[1];
    const float* embed   = (const float*)d_in[2];
    const float* enc_Wih = (const float*)d_in[3];
    const float* enc_Whh = (const float*)d_in[4];
    const float* enc_bih = (const float*)d_in[5];
    const float* enc_bhh = (const float*)d_in[6];
    const float* dec_Wih = (const float*)d_in[7];
    const float* dec_Whh = (const float*)d_in[8];
    const float* dec_bih = (const float*)d_in[9];
    const float* dec_bhh = (const float*)d_in[10];
    const float* attn_W  = (const float*)d_in[11];
    const float* attn_b  = (const float*)d_in[12];
    const float* attn_v  = (const float*)d_in[13];
    const float* fc_W    = (const float*)d_in[14];
    const float* fc_b    = (const float*)d_in[15];
    float* out = (float*)d_out;

    float *p_src_emb, *p_dec_in, *p_enc_xg, *p_dec_xg, *p_enc_out, *p_enc_proj;
    cudaGetSymbolAddress((void**)&p_src_emb,  g_src_emb);
    cudaGetSymbolAddress((void**)&p_dec_in,   g_dec_in);
    cudaGetSymbolAddress((void**)&p_enc_xg,   g_enc_xg);
    cudaGetSymbolAddress((void**)&p_dec_xg,   g_dec_xg);
    cudaGetSymbolAddress((void**)&p_enc_out,  g_enc_out);
    cudaGetSymbolAddress((void**)&p_enc_proj, g_enc_proj);

    cudaFuncSetAttribute(enc_scan_kernel, cudaFuncAttributeMaxDynamicSharedMemorySize, ENC_SMEM_BYTES);
    cudaFuncSetAttribute(dec_scan_kernel, cudaFuncAttributeMaxDynamicSharedMemorySize, DEC_SMEM_BYTES);
    cudaFuncSetAttribute(fc_mma_kernel,  cudaFuncAttributeMaxDynamicSharedMemorySize, FC_SMEM_BYTES);

    init_state_kernel<<<(Bsz * Hd + 255) / 256, 256>>>();
    gather_src_kernel<<<Ssz * Bsz, Ed>>>(src, embed);
    gather_dec_kernel<<<T1 * Bsz, Ed>>>(tgt, embed);

    // fc_W bf16-split (independent; overlaps pipeline head)
    conv_w_kernel<<<(Vsz * Hd / 4 + 255) / 256, 256>>>(fc_W);

    {   // enc_xg
        dim3 grid(FH / 128, (Ssz * Bsz + 127) / 128);
        sgemm_bias_kernel<<<grid, 256>>>(p_src_emb, Ed, enc_Wih, Ed, 0,
                                         enc_bih, enc_bhh, p_enc_xg, Ssz * Bsz, FH);
    }
    {   // dec_xg
        dim3 grid(FH / 128, (T1 * Bsz + 127) / 128);
        sgemm_bias_kernel<<<grid, 256>>>(p_dec_in, Ed, dec_Wih, Ed + Hd, 0,
                                         dec_bih, dec_bhh, p_dec_xg, T1 * Bsz, FH);
    }

    enc_scan_kernel<<<NBLK, 256, ENC_SMEM_BYTES>>>(enc_Whh);

    {   // enc_proj
        dim3 grid(Hd / 128, (Bsz * Ssz + 127) / 128);
        sgemm_bias_kernel<<<grid, 256>>>(p_enc_out, Hd, attn_W, 2 * Hd, Hd,
                                         attn_b, nullptr, p_enc_proj, Bsz * Ssz, Hd);
    }

    dec_scan_kernel<<<NBLK, 256, DEC_SMEM_BYTES>>>(dec_Wih, dec_Whh, attn_W, attn_v);

    conv_hs_kernel<<<(MrowsPad * Hd / 4 + 255) / 256, 256>>>();
    fc_mma_kernel<<<dim3(MrowsPad / 128, Vsz / 128), 256, FC_SMEM_BYTES>>>(fc_b, out);
}

// round 7
// speedup vs baseline: 3.3449x; 1.0014x over previous
#include <cuda_runtime.h>
#include <cuda_bf16.h>
#include <cstddef>
#include <cstdint>

#define Bsz 32
#define Ssz 128
#define Tsz 64
#define T1  63
#define Ed  256
#define Hd  512
#define Vsz 32000
#define FH  2048
#define NBLK 128
#define Mrows 2016       // Bsz*T1
#define MrowsPad 2048

// ---------------- device scratch ----------------
__device__ __align__(16) float g_src_emb[(size_t)Ssz * Bsz * Ed];
__device__ __align__(16) float g_dec_in [(size_t)T1  * Bsz * Ed];
__device__ __align__(16) float g_enc_xg [(size_t)Ssz * Bsz * FH];
__device__ __align__(16) float g_dec_xg [(size_t)T1  * Bsz * FH];
__device__ __align__(16) float g_enc_out[(size_t)Bsz * Ssz * Hd];
__device__ __align__(16) float g_enc_proj[(size_t)Bsz * Ssz * Hd];
__device__ __align__(16) float g_hs     [(size_t)Bsz * T1  * Hd];
__device__ __align__(16) float g_h[2][Bsz * Hd];
__device__ __align__(16) float g_c [Bsz * Hd];
__device__ __align__(16) float g_ctx[Bsz * Hd];
__device__ __align__(16) float g_hproj[Bsz * Hd];
__device__ __align__(16) float g_scores[Bsz * Ssz];
__device__ unsigned g_cnt[2];
__device__ unsigned g_gen[2];
// bf16 hi/lo split operands for the FC tensor GEMM
__device__ __align__(16) __nv_bfloat16 g_hs_hi[(size_t)MrowsPad * Hd];
__device__ __align__(16) __nv_bfloat16 g_hs_lo[(size_t)MrowsPad * Hd];
__device__ __align__(16) __nv_bfloat16 g_fcw_hi[(size_t)Vsz * Hd];
__device__ __align__(16) __nv_bfloat16 g_fcw_lo[(size_t)Vsz * Hd];

__device__ __forceinline__ float sigf(float x) { return 1.0f / (1.0f + expf(-x)); }

// ---------------- packed f32x2 FMA (SASS FFMA2, sm_100+ baseline PTX) ----------------
__device__ __forceinline__ void ffma2(unsigned long long& d, unsigned long long a, unsigned long long b) {
    asm("fma.rn.f32x2 %0, %1, %2, %0;" : "+l"(d) : "l"(a), "l"(b));
}
__device__ __forceinline__ float f32x2_sum(unsigned long long v) {
    float lo, hi;
    asm("mov.b64 {%0, %1}, %2;" : "=f"(lo), "=f"(hi) : "l"(v));
    return lo + hi;
}
__device__ __forceinline__ void f32x2_unpack(unsigned long long v, float& lo, float& hi) {
    asm("mov.b64 {%0, %1}, %2;" : "=f"(lo), "=f"(hi) : "l"(v));
}
__device__ __forceinline__ unsigned long long pack2(float lo, float hi) {
    unsigned long long v;
    asm("mov.b64 %0, {%1, %2};" : "=l"(v) : "f"(lo), "f"(hi));
    return v;
}

__device__ __forceinline__ uint32_t smem_to_u32(const void* p) {
    uint32_t a;
    asm("{ .reg .u64 t; cvta.to.shared.u64 t, %1; cvt.u32.u64 %0, t; }" : "=r"(a) : "l"(p));
    return a;
}
__device__ __forceinline__ void ldsm_x4(uint32_t* r, uint32_t addr) {
    asm volatile("ldmatrix.sync.aligned.m8n8.x4.shared.b16 {%0,%1,%2,%3}, [%4];"
        : "=r"(r[0]), "=r"(r[1]), "=r"(r[2]), "=r"(r[3]) : "r"(addr));
}
__device__ __forceinline__ void mma_bf16(float* d, const uint32_t* a, uint32_t b0, uint32_t b1) {
    asm volatile("mma.sync.aligned.m16n8k16.row.col.f32.bf16.bf16.f32 "
        "{%0,%1,%2,%3}, {%4,%5,%6,%7}, {%8,%9}, {%0,%1,%2,%3};"
        : "+f"(d[0]), "+f"(d[1]), "+f"(d[2]), "+f"(d[3])
        : "r"(a[0]), "r"(a[1]), "r"(a[2]), "r"(a[3]), "r"(b0), "r"(b1));
}
__device__ __forceinline__ void cp_async16(uint32_t dst, const void* src) {
    asm volatile("cp.async.cg.shared.global [%0], [%1], 16;" :: "r"(dst), "l"(src) : "memory");
}

// ---------------- global barrier across NBLK co-resident blocks ----------------
__device__ __forceinline__ void grid_bar(int which, unsigned target) {
    __threadfence();
    __syncthreads();
    if (threadIdx.x == 0) {
        unsigned arr = atomicAdd(&g_cnt[which], 1u);
        if (arr == NBLK - 1u) {
            g_cnt[which] = 0u;
            __threadfence();
            atomicAdd(&g_gen[which], 1u);
        } else {
            while (atomicAdd(&g_gen[which], 0u) < target) { }
        }
    }
    __syncthreads();
}

__global__ void init_state_kernel() {
    int i = blockIdx.x * blockDim.x + threadIdx.x;
    if (i < Bsz * Hd) g_h[0][i] = 0.f;
    if (i < 2) { g_cnt[i] = 0u; g_gen[i] = 0u; }
}

// ---------------- embedding gathers ----------------
__global__ void gather_src_kernel(const int* __restrict__ src, const float* __restrict__ embed) {
    int row = blockIdx.x;           // s*B + b
    int s = row >> 5, b = row & 31;
    int idx = src[b * Ssz + s];
    g_src_emb[(size_t)row * Ed + threadIdx.x] = embed[(size_t)idx * Ed + threadIdx.x];
}
__global__ void gather_dec_kernel(const int* __restrict__ tgt, const float* __restrict__ embed) {
    int row = blockIdx.x;           // t*B + b
    int t = row >> 5, b = row & 31;
    int idx = tgt[b * Tsz + t];
    g_dec_in[(size_t)row * Ed + threadIdx.x] = embed[(size_t)idx * Ed + threadIdx.x];
}

// ---------------- fp32 SGEMM with f32x2 FMA (small GEMMs) ----------------
__global__ void __launch_bounds__(256) sgemm_bias_kernel(
    const float* __restrict__ A, int K,
    const float* __restrict__ W, int ldw, int woff,
    const float* __restrict__ b1, const float* __restrict__ b2,
    float* __restrict__ C, int M, int N)
{
    __shared__ __align__(16) float As[8][128];
    __shared__ __align__(16) float Bs[8][128];
    const int bm = blockIdx.y * 128;
    const int bn = blockIdx.x * 128;
    const int t  = threadIdx.x;
    const int tr = (t >> 4) * 8;
    const int tc = (t & 15) * 8;
    const int lr = t >> 1;
    const int lc = (t & 1) * 4;

    unsigned long long acc2[8][4];
    #pragma unroll
    for (int i = 0; i < 8; i++)
        #pragma unroll
        for (int j = 0; j < 4; j++) acc2[i][j] = 0ull;

    const bool aValid = (bm + lr) < M;
    const float* aRow = A + (size_t)(bm + lr) * K + lc;
    const float* wRow = W + (size_t)(bn + lr) * ldw + woff + lc;

    for (int k0 = 0; k0 < K; k0 += 8) {
        float4 av = aValid ? *(const float4*)(aRow + k0) : make_float4(0.f, 0.f, 0.f, 0.f);
        float4 wv = *(const float4*)(wRow + k0);
        As[lc + 0][lr] = av.x; As[lc + 1][lr] = av.y; As[lc + 2][lr] = av.z; As[lc + 3][lr] = av.w;
        Bs[lc + 0][lr] = wv.x; Bs[lc + 1][lr] = wv.y; Bs[lc + 2][lr] = wv.z; Bs[lc + 3][lr] = wv.w;
        __syncthreads();
        #pragma unroll
        for (int kk = 0; kk < 8; kk++) {
            float a[8];
            *(float4*)(a)      = *(const float4*)&As[kk][tr];
            *(float4*)(a + 4)  = *(const float4*)&As[kk][tr + 4];
            unsigned long long bb2[4];
            *(ulonglong2*)&bb2[0] = *(const ulonglong2*)&Bs[kk][tc];
            *(ulonglong2*)&bb2[2] = *(const ulonglong2*)&Bs[kk][tc + 4];
            #pragma unroll
            for (int i = 0; i < 8; i++) {
                unsigned long long ap = pack2(a[i], a[i]);
                #pragma unroll
                for (int j = 0; j < 4; j++) ffma2(acc2[i][j], ap, bb2[j]);
            }
        }
        __syncthreads();
    }

    float bias[8];
    #pragma unroll
    for (int j = 0; j < 8; j++) {
        int n = bn + tc + j;
        bias[j] = b1[n] + (b2 ? b2[n] : 0.f);
    }
    #pragma unroll
    for (int i = 0; i < 8; i++) {
        int m = bm + tr + i;
        if (m >= M) break;
        float* cp = C + (size_t)m * N + bn + tc;
        #pragma unroll
        for (int j = 0; j < 4; j++) {
            float lo, hi;
            f32x2_unpack(acc2[i][j], lo, hi);
            cp[j * 2]     = lo + bias[j * 2];
            cp[j * 2 + 1] = hi + bias[j * 2 + 1];
        }
    }
}

// ---------------- gate partial-GEMM helper (f32x2) ----------------
// 16 weight rows at wbase (stride 516); 32x512 x-tile at xbase (stride 516).
__device__ __forceinline__ void gates_partial(
    const float* sm, int wbase, int xbase, int jg, int bg, int ks, unsigned long long acc[4][4])
{
    const int k0 = ks * 64;
    #pragma unroll 4
    for (int k4 = 0; k4 < 16; k4++) {
        const int k = k0 + (k4 << 2);
        ulonglong2 wv[4], hv[4];
        #pragma unroll
        for (int jj = 0; jj < 4; jj++)
            wv[jj] = *(const ulonglong2*)&sm[wbase + (jj * 4 + jg) * 516 + k];
        #pragma unroll
        for (int bb = 0; bb < 4; bb++)
            hv[bb] = *(const ulonglong2*)&sm[xbase + (bb * 8 + bg) * 516 + k];
        #pragma unroll
        for (int jj = 0; jj < 4; jj++)
            #pragma unroll
            for (int bb = 0; bb < 4; bb++) {
                ffma2(acc[jj][bb], wv[jj].x, hv[bb].x);
                ffma2(acc[jj][bb], wv[jj].y, hv[bb].y);
            }
    }
}

// ---------------- persistent encoder scan ----------------
#define ENC_SMEM_BYTES (28992 * 4)
__global__ void __launch_bounds__(256, 1) enc_scan_kernel(const float* __restrict__ Whh) {
    extern __shared__ float sm[];
    const int tid = threadIdx.x, hG = blockIdx.x;
    const int W0 = 0, HX = 8256, RD = 24768;

    for (int i = tid; i < 16 * 128; i += 256) {
        int r = i >> 7, k4 = i & 127;
        int j = (r >> 2) * Hd + hG * 4 + (r & 3);
        *(float4*)&sm[W0 + r * 516 + k4 * 4] = *(const float4*)&Whh[(size_t)j * Hd + k4 * 4];
    }

    float c_reg = 0.f;
    const int jg = tid & 3, bg = (tid >> 2) & 7, ks = tid >> 5;
    unsigned bgen = 0;

    for (int s = 0; s < Ssz; s++) {
        const float* hin = g_h[s & 1];
        float* hout = g_h[(s + 1) & 1];
        for (int i = tid; i < 32 * 128; i += 256) {
            int b = i >> 7, k4 = i & 127;
            *(float4*)&sm[HX + b * 516 + k4 * 4] = __ldcg((const float4*)&hin[(b << 9) + k4 * 4]);
        }
        __syncthreads();

        unsigned long long acc[4][4];
        #pragma unroll
        for (int a = 0; a < 4; a++)
            #pragma unroll
            for (int b2 = 0; b2 < 4; b2++) acc[a][b2] = 0ull;
        gates_partial(sm, W0, HX, jg, bg, ks, acc);

        #pragma unroll
        for (int jj = 0; jj < 4; jj++)
            #pragma unroll
            for (int bb = 0; bb < 4; bb++)
                sm[RD + ks * 528 + (jj * 4 + jg) * 33 + bb * 8 + bg] = f32x2_sum(acc[jj][bb]);
        __syncthreads();

        if (tid < 128) {
            const int hl = tid >> 5, b = tid & 31;
            float g4[4];
            #pragma unroll
            for (int gate = 0; gate < 4; gate++) {
                int r = gate * 4 + hl;
                float a = 0.f;
                #pragma unroll
                for (int q = 0; q < 8; q++) a += sm[RD + q * 528 + r * 33 + b];
                g4[gate] = a + g_enc_xg[((size_t)s * Bsz + b) * FH + gate * Hd + hG * 4 + hl];
            }
            float cv = sigf(g4[1]) * c_reg + sigf(g4[0]) * tanhf(g4[2]);
            float hn = sigf(g4[3]) * tanhf(cv);
            c_reg = cv;
            hout[(b << 9) + hG * 4 + hl] = hn;
            g_enc_out[((size_t)b * Ssz + s) * Hd + hG * 4 + hl] = hn;
        }
        bgen++;
        grid_bar(0, bgen);
    }
    if (tid < 128) {
        const int hl = tid >> 5, b = tid & 31;
        g_c[(b << 9) + hG * 4 + hl] = c_reg;
    }
}

// ---------------- persistent decoder scan (attention fused) ----------------
#define DEC_SMEM_BYTES (40464 * 4)
__global__ void __launch_bounds__(256, 1) dec_scan_kernel(
    const float* __restrict__ Wih, const float* __restrict__ Whh,
    const float* __restrict__ attnW, const float* __restrict__ attnv)
{
    extern __shared__ float sm[];
    const int tid = threadIdx.x, hG = blockIdx.x;
    const int W0 = 0, WC = 8256, WA = 16512, HX = 18576, RD = 35088,
              HP = 39312, VS = 39824, SC = 40336;

    for (int i = tid; i < 16 * 128; i += 256) {
        int r = i >> 7, k4 = i & 127;
        int j = (r >> 2) * Hd + hG * 4 + (r & 3);
        *(float4*)&sm[W0 + r * 516 + k4 * 4] = *(const float4*)&Whh[(size_t)j * Hd + k4 * 4];
        *(float4*)&sm[WC + r * 516 + k4 * 4] = *(const float4*)&Wih[(size_t)j * (Ed + Hd) + Ed + k4 * 4];
    }
    for (int i = tid; i < 4 * 128; i += 256) {
        int r = i >> 7, k4 = i & 127;
        *(float4*)&sm[WA + r * 516 + k4 * 4] = *(const float4*)&attnW[(size_t)(hG * 4 + r) * (2 * Hd) + k4 * 4];
    }
    for (int i = tid; i < Hd; i += 256) sm[VS + i] = attnv[i];

    float c_reg = 0.f;
    if (tid < 128) {
        const int hl = tid >> 5, b = tid & 31;
        c_reg = __ldcg(&g_c[(b << 9) + hG * 4 + hl]);
    }

    const int jg = tid & 3, bg = (tid >> 2) & 7, ks = tid >> 5;
    const int bB = hG >> 2;
    unsigned bgen = 0;

    for (int t = 0; t < T1; t++) {
        const float* hin = g_h[t & 1];
        float* hout = g_h[(t + 1) & 1];

        // ---- phase A ----
        for (int i = tid; i < 32 * 128; i += 256) {
            int b = i >> 7, k4 = i & 127;
            *(float4*)&sm[HX + b * 516 + k4 * 4] = __ldcg((const float4*)&hin[(b << 9) + k4 * 4]);
        }
        __syncthreads();
        {
            const int ko = tid >> 6, bh = (tid >> 1) & 31, kh = tid & 1;
            float a = 0.f;
            const int kb = kh << 8;
            #pragma unroll 4
            for (int k = kb; k < kb + 256; k += 4) {
                float4 w4 = *(const float4*)&sm[WA + ko * 516 + k];
                float4 h4 = *(const float4*)&sm[HX + bh * 516 + k];
                a += w4.x * h4.x + w4.y * h4.y + w4.z * h4.z + w4.w * h4.w;
            }
            a += __shfl_xor_sync(0xffffffffu, a, 1);
            if (!kh) g_hproj[(bh << 9) + hG * 4 + ko] = a;
        }
        unsigned long long acc[4][4];
        #pragma unroll
        for (int a2 = 0; a2 < 4; a2++)
            #pragma unroll
            for (int b2 = 0; b2 < 4; b2++) acc[a2][b2] = 0ull;
        gates_partial(sm, W0, HX, jg, bg, ks, acc);
        bgen++; grid_bar(1, bgen);

        // ---- phase B ----
        for (int i = tid; i < Hd; i += 256) sm[HP + i] = __ldcg(&g_hproj[(bB << 9) + i]);
        __syncthreads();
        {
            const int s0 = (hG & 3) * 32, w = tid >> 5, lane = tid & 31;
            #pragma unroll
            for (int q = 0; q < 4; q++) {
                int s2 = s0 + w * 4 + q;
                const float* ep = g_enc_proj + ((size_t)bB * Ssz + s2) * Hd;
                float a = 0.f;
                for (int kk = lane; kk < Hd; kk += 32)
                    a += tanhf(sm[HP + kk] + ep[kk]) * sm[VS + kk];
                #pragma unroll
                for (int off = 16; off; off >>= 1) a += __shfl_xor_sync(0xffffffffu, a, off);
                if (!lane) g_scores[bB * Ssz + s2] = a;
            }
        }
        bgen++; grid_bar(1, bgen);

        // ---- phase C ----
        if (tid < 128) sm[SC + tid] = __ldcg(&g_scores[bB * Ssz + tid]);
        __syncthreads();
        float m = -1e30f;
        for (int i2 = 0; i2 < 128; i2++) m = fmaxf(m, sm[SC + i2]);
        __syncthreads();
        if (tid < 128) sm[SC + tid] = expf(sm[SC + tid] - m);
        __syncthreads();
        float ssum = 0.f;
        for (int i2 = 0; i2 < 128; i2++) ssum += sm[SC + i2];
        {
            const float inv = 1.f / ssum;
            const int h0 = (hG & 3) * 128, h = h0 + (tid >> 1), sh = tid & 1;
            const float* eo = g_enc_out + ((size_t)bB * Ssz + (sh << 6)) * Hd + h;
            float a = 0.f;
            #pragma unroll 4
            for (int s2 = 0; s2 < 64; s2++) a += sm[SC + (sh << 6) + s2] * eo[(size_t)s2 * Hd];
            a += __shfl_xor_sync(0xffffffffu, a, 1);
            if (!sh) g_ctx[(bB << 9) + h] = a * inv;
        }
        bgen++; grid_bar(1, bgen);

        // ---- phase D ----
        for (int i = tid; i < 32 * 128; i += 256) {
            int b = i >> 7, k4 = i & 127;
            *(float4*)&sm[HX + b * 516 + k4 * 4] = __ldcg((const float4*)&g_ctx[(b << 9) + k4 * 4]);
        }
        __syncthreads();
        gates_partial(sm, WC, HX, jg, bg, ks, acc);

        #pragma unroll
        for (int jj = 0; jj < 4; jj++)
            #pragma unroll
            for (int bb = 0; bb < 4; bb++)
                sm[RD + ks * 528 + (jj * 4 + jg) * 33 + bb * 8 + bg] = f32x2_sum(acc[jj][bb]);
        __syncthreads();

        if (tid < 128) {
            const int hl = tid >> 5, b = tid & 31;
            float g4[4];
            #pragma unroll
            for (int gate = 0; gate < 4; gate++) {
                int r = gate * 4 + hl;
                float a = 0.f;
                #pragma unroll
                for (int q = 0; q < 8; q++) a += sm[RD + q * 528 + r * 33 + b];
                g4[gate] = a + g_dec_xg[((size_t)t * Bsz + b) * FH + gate * Hd + hG * 4 + hl];
            }
            float cv = sigf(g4[1]) * c_reg + sigf(g4[0]) * tanhf(g4[2]);
            float hn = sigf(g4[3]) * tanhf(cv);
            c_reg = cv;
            hout[(b << 9) + hG * 4 + hl] = hn;
            g_hs[((size_t)b * T1 + t) * Hd + hG * 4 + hl] = hn;
        }
        bgen++; grid_bar(1, bgen);
    }
}

// ---------------- bf16 hi/lo split conversions ----------------
__global__ void conv_hs_kernel() {
    size_t i = ((size_t)blockIdx.x * 256 + threadIdx.x) * 4;
    if (i >= (size_t)MrowsPad * Hd) return;
    float4 x = (i < (size_t)Mrows * Hd) ? *(const float4*)&g_hs[i] : make_float4(0.f, 0.f, 0.f, 0.f);
    float v[4] = {x.x, x.y, x.z, x.w};
    #pragma unroll
    for (int j = 0; j < 4; j++) {
        __nv_bfloat16 hi = __float2bfloat16(v[j]);
        g_hs_hi[i + j] = hi;
        g_hs_lo[i + j] = __float2bfloat16(v[j] - __bfloat162float(hi));
    }
}
__global__ void conv_w_kernel(const float* __restrict__ fc_W) {
    size_t i = ((size_t)blockIdx.x * 256 + threadIdx.x) * 4;
    if (i >= (size_t)Vsz * Hd) return;
    float4 x = *(const float4*)&fc_W[i];
    float v[4] = {x.x, x.y, x.z, x.w};
    #pragma unroll
    for (int j = 0; j < 4; j++) {
        __nv_bfloat16 hi = __float2bfloat16(v[j]);
        g_fcw_hi[i + j] = hi;
        g_fcw_lo[i + j] = __float2bfloat16(v[j] - __bfloat162float(hi));
    }
}

// ---------------- FC GEMM via mma.sync bf16 (hi/lo split), cp.async 2-stage ----------------
// CTA: 128x128 tile. 8 warps = 4(m) x 2(n); warp tile 32x64.
// K=512 in 8 chunks of 64; 2-stage cp.async pipeline over chunks.
// smem per stage: 4 tiles (Ah, Al, Bh, Bl), each 128 rows x 72 bf16 (144B row).
#define FC_TS 9216                       // bf16 elems per tile (128*72)
#define FC_STAGE (4 * FC_TS)             // bf16 elems per stage
#define FC_SMEM_BYTES (2 * FC_STAGE * 2) // 147456
__global__ void __launch_bounds__(256, 1) fc_mma_kernel(
    const float* __restrict__ fc_b, float* __restrict__ out)
{
    extern __shared__ __nv_bfloat16 smb[];
    const int tid = threadIdx.x, lane = tid & 31, wid = tid >> 5;
    const int wm = wid & 3, wn = wid >> 2;
    const int m0 = blockIdx.x * 128, n0 = blockIdx.y * 128;
    const uint32_t smem_base = smem_to_u32(smb);

    const __nv_bfloat16* base0 = g_hs_hi  + (size_t)m0 * Hd;
    const __nv_bfloat16* base1 = g_hs_lo  + (size_t)m0 * Hd;
    const __nv_bfloat16* base2 = g_fcw_hi + (size_t)n0 * Hd;
    const __nv_bfloat16* base3 = g_fcw_lo + (size_t)n0 * Hd;

    float acc[2][8][4];
    #pragma unroll
    for (int a = 0; a < 2; a++)
        #pragma unroll
        for (int b = 0; b < 8; b++)
            #pragma unroll
            for (int c = 0; c < 4; c++) acc[a][b][c] = 0.f;

    const int lrow = ((lane >> 3) & 1) * 8 + (lane & 7);
    const int lcol = (lane >> 4) * 8;

    auto issue_stage = [&](int kc, int stg) {
        uint32_t sbase = smem_base + (uint32_t)stg * (FC_STAGE * 2);
        #pragma unroll
        for (int tt = 0; tt < 4; tt++) {
            int idx = tid + tt * 256;
            int r = idx >> 3, c8 = idx & 7;
            uint32_t doff = (uint32_t)(r * 144 + c8 * 16);
            size_t gi = (size_t)r * Hd + kc * 64 + c8 * 8;
            cp_async16(sbase + doff,                    base0 + gi);
            cp_async16(sbase + FC_TS * 2 + doff,        base1 + gi);
            cp_async16(sbase + FC_TS * 4 + doff,        base2 + gi);
            cp_async16(sbase + FC_TS * 6 + doff,        base3 + gi);
        }
        asm volatile("cp.async.commit_group;" ::: "memory");
    };

    issue_stage(0, 0);

    for (int kc = 0; kc < 8; kc++) {
        const int stg = kc & 1;
        if (kc < 7) {
            issue_stage(kc + 1, stg ^ 1);
            asm volatile("cp.async.wait_group 1;" ::: "memory");
        } else {
            asm volatile("cp.async.wait_group 0;" ::: "memory");
        }
        __syncthreads();

        const uint32_t sb = smem_base + (uint32_t)stg * (FC_STAGE * 2);
        #pragma unroll
        for (int kk = 0; kk < 4; kk++) {
            uint32_t ah[2][4], al[2][4];
            #pragma unroll
            for (int mt = 0; mt < 2; mt++) {
                uint32_t off = sb + (uint32_t)(((wm * 32 + mt * 16 + lrow) * 72 + kk * 16 + lcol) * 2);
                ldsm_x4(ah[mt], off);
                ldsm_x4(al[mt], off + FC_TS * 2);
            }
            #pragma unroll
            for (int ng = 0; ng < 4; ng++) {
                uint32_t off = sb + (uint32_t)(((wn * 64 + ng * 16 + lrow) * 72 + kk * 16 + lcol) * 2);
                uint32_t bh[4], bl[4];
                ldsm_x4(bh, off + FC_TS * 4);
                ldsm_x4(bl, off + FC_TS * 6);
                #pragma unroll
                for (int mt = 0; mt < 2; mt++) {
                    mma_bf16(acc[mt][ng * 2],     ah[mt], bh[0], bh[2]);
                    mma_bf16(acc[mt][ng * 2],     ah[mt], bl[0], bl[2]);
                    mma_bf16(acc[mt][ng * 2],     al[mt], bh[0], bh[2]);
                    mma_bf16(acc[mt][ng * 2 + 1], ah[mt], bh[1], bh[3]);
                    mma_bf16(acc[mt][ng * 2 + 1], ah[mt], bl[1], bl[3]);
                    mma_bf16(acc[mt][ng * 2 + 1], al[mt], bh[1], bh[3]);
                }
            }
        }
        __syncthreads();
    }

    // epilogue: d frag: (d0,d1)@row lane/4, cols (lane&3)*2..+1; (d2,d3)@row+8
    const int rbase = m0 + wm * 32 + (lane >> 2);
    const int cbase = n0 + wn * 64 + (lane & 3) * 2;
    #pragma unroll
    for (int mt = 0; mt < 2; mt++)
        #pragma unroll
        for (int nt = 0; nt < 8; nt++) {
            int c = cbase + nt * 8;
            float b0 = fc_b[c], b1 = fc_b[c + 1];
            int r0 = rbase + mt * 16;
            if (r0 < Mrows) {
                float2 v = make_float2(acc[mt][nt][0] + b0, acc[mt][nt][1] + b1);
                *(float2*)&out[(size_t)r0 * Vsz + c] = v;
            }
            int r1 = r0 + 8;
            if (r1 < Mrows) {
                float2 v = make_float2(acc[mt][nt][2] + b0, acc[mt][nt][3] + b1);
                *(float2*)&out[(size_t)r1 * Vsz + c] = v;
            }
        }
}

// ---------------- launch ----------------
extern "C" void kernel_launch(void* const* d_in, const int* in_sizes, int n_in,
                              void* d_out, int out_size)
{
    const int*   src     = (const int*)d_in[0];
    const int*   tgt     = (const int*)d_in[1];
    const float* embed   = (const float*)d_in[2];
    const float* enc_Wih = (const float*)d_in[3];
    const float* enc_Whh = (const float*)d_in[4];
    const float* enc_bih = (const float*)d_in[5];
    const float* enc_bhh = (const float*)d_in[6];
    const float* dec_Wih = (const float*)d_in[7];
    const float* dec_Whh = (const float*)d_in[8];
    const float* dec_bih = (const float*)d_in[9];
    const float* dec_bhh = (const float*)d_in[10];
    const float* attn_W  = (const float*)d_in[11];
    const float* attn_b  = (const float*)d_in[12];
    const float* attn_v  = (const float*)d_in[13];
    const float* fc_W    = (const float*)d_in[14];
    const float* fc_b    = (const float*)d_in[15];
    float* out = (float*)d_out;

    float *p_src_emb, *p_dec_in, *p_enc_xg, *p_dec_xg, *p_enc_out, *p_enc_proj;
    cudaGetSymbolAddress((void**)&p_src_emb,  g_src_emb);
    cudaGetSymbolAddress((void**)&p_dec_in,   g_dec_in);
    cudaGetSymbolAddress((void**)&p_enc_xg,   g_enc_xg);
    cudaGetSymbolAddress((void**)&p_dec_xg,   g_dec_xg);
    cudaGetSymbolAddress((void**)&p_enc_out,  g_enc_out);
    cudaGetSymbolAddress((void**)&p_enc_proj, g_enc_proj);

    cudaFuncSetAttribute(enc_scan_kernel, cudaFuncAttributeMaxDynamicSharedMemorySize, ENC_SMEM_BYTES);
    cudaFuncSetAttribute(dec_scan_kernel, cudaFuncAttributeMaxDynamicSharedMemorySize, DEC_SMEM_BYTES);
    cudaFuncSetAttribute(fc_mma_kernel,  cudaFuncAttributeMaxDynamicSharedMemorySize, FC_SMEM_BYTES);

    init_state_kernel<<<(Bsz * Hd + 255) / 256, 256>>>();
    gather_src_kernel<<<Ssz * Bsz, Ed>>>(src, embed);
    gather_dec_kernel<<<T1 * Bsz, Ed>>>(tgt, embed);

    // fc_W bf16-split (independent; overlaps pipeline head)
    conv_w_kernel<<<(Vsz * Hd / 4 + 255) / 256, 256>>>(fc_W);

    {   // enc_xg
        dim3 grid(FH / 128, (Ssz * Bsz + 127) / 128);
        sgemm_bias_kernel<<<grid, 256>>>(p_src_emb, Ed, enc_Wih, Ed, 0,
                                         enc_bih, enc_bhh, p_enc_xg, Ssz * Bsz, FH);
    }
    {   // dec_xg
        dim3 grid(FH / 128, (T1 * Bsz + 127) / 128);
        sgemm_bias_kernel<<<grid, 256>>>(p_dec_in, Ed, dec_Wih, Ed + Hd, 0,
                                         dec_bih, dec_bhh, p_dec_xg, T1 * Bsz, FH);
    }

    enc_scan_kernel<<<NBLK, 256, ENC_SMEM_BYTES>>>(enc_Whh);

    {   // enc_proj
        dim3 grid(Hd / 128, (Bsz * Ssz + 127) / 128);
        sgemm_bias_kernel<<<grid, 256>>>(p_enc_out, Hd, attn_W, 2 * Hd, Hd,
                                         attn_b, nullptr, p_enc_proj, Bsz * Ssz, Hd);
    }

    dec_scan_kernel<<<NBLK, 256, DEC_SMEM_BYTES>>>(dec_Wih, dec_Whh, attn_W, attn_v);

    conv_hs_kernel<<<(MrowsPad * Hd / 4 + 255) / 256, 256>>>();
    fc_mma_kernel<<<dim3(MrowsPad / 128, Vsz / 128), 256, FC_SMEM_BYTES>>>(fc_b, out);
}